// round 12
// baseline (speedup 1.0000x reference)
#include <cuda_runtime.h>
#include <cuda_bf16.h>
#include <math.h>
#include <cstdint>

#define BB 64
#define TT 1024
#define DD 256
#define HH 128
#define G4 512           // 4*H gate width
#define NTAGS 3
#define M_TOTAL (BB*TT)  // 65536

typedef unsigned long long u64;

// single dynamic-shared extern for all kernels
extern __shared__ char smem_raw[];

// ---------------- static scratch (no allocs allowed) ----------------
__device__ float g_gx[(size_t)2 * BB * TT * G4];        // [dir][b][t][512]
__device__ float g_seq1[(size_t)BB * TT * 2 * HH];      // layer1 output (fp32)
__device__ float g_part[BB];
__device__ __nv_bfloat16 g_xhi[(size_t)M_TOTAL * DD];   // A hi
__device__ __nv_bfloat16 g_xlo[(size_t)M_TOTAL * DD];   // A lo
__device__ __nv_bfloat16 g_whi[(size_t)4 * G4 * DD];    // W hi (l0,l0r,l1,l1r)
__device__ __nv_bfloat16 g_wlo[(size_t)4 * G4 * DD];    // W lo

// fast sigmoid / tanh (err ~2^-20)
__device__ __forceinline__ float fsig(float x) {
    return __fdividef(1.0f, 1.0f + __expf(-x));
}
__device__ __forceinline__ float ftanh_id(float x) {   // 2*sig(2x)-1
    return fmaf(2.0f, __fdividef(1.0f, 1.0f + __expf(-2.0f * x)), -1.0f);
}

// ---- packed f32x2 helpers ----
__device__ __forceinline__ void fma2(u64& d, u64 a, u64 b) {
    asm("fma.rn.f32x2 %0, %1, %2, %0;" : "+l"(d) : "l"(a), "l"(b));
}
__device__ __forceinline__ void add2(u64& d, u64 a, u64 b) {
    asm("add.rn.f32x2 %0, %1, %2;" : "=l"(d) : "l"(a), "l"(b));
}
__device__ __forceinline__ float2 unpk(u64 v) {
    float2 f; asm("mov.b64 {%0, %1}, %2;" : "=f"(f.x), "=f"(f.y) : "l"(v)); return f;
}

__device__ __forceinline__ uint32_t smem_u32(const void* p) {
    uint32_t a;
    asm("{ .reg .u64 t; cvta.to.shared.u64 t, %1; cvt.u32.u64 %0, t; }" : "=r"(a) : "l"(p));
    return a;
}

// ---- ldmatrix / mma.sync / cp.async (base sm_80+ ISA) ----
__device__ __forceinline__ void ldm_x4(uint32_t* r, uint32_t addr) {
    asm volatile("ldmatrix.sync.aligned.m8n8.x4.shared.b16 {%0,%1,%2,%3}, [%4];"
        : "=r"(r[0]), "=r"(r[1]), "=r"(r[2]), "=r"(r[3]) : "r"(addr));
}
__device__ __forceinline__ void mma_bf16(float* d, const uint32_t* a, uint32_t b0, uint32_t b1) {
    asm volatile("mma.sync.aligned.m16n8k16.row.col.f32.bf16.bf16.f32 "
        "{%0,%1,%2,%3}, {%4,%5,%6,%7}, {%8,%9}, {%0,%1,%2,%3};"
        : "+f"(d[0]), "+f"(d[1]), "+f"(d[2]), "+f"(d[3])
        : "r"(a[0]), "r"(a[1]), "r"(a[2]), "r"(a[3]), "r"(b0), "r"(b1));
}
__device__ __forceinline__ void cpa16(uint32_t dst, const void* src) {
    asm volatile("cp.async.cg.shared.global [%0], [%1], 16;" :: "r"(dst), "l"(src));
}

// =====================================================================
// fp32 -> bf16 hi/lo split (vectorized x4)
// =====================================================================
__device__ __forceinline__ void cvt_one4(const float4& v,
                                         __nv_bfloat162* hp, __nv_bfloat162* lp, int i)
{
    __nv_bfloat16 h0 = __float2bfloat16(v.x), h1 = __float2bfloat16(v.y);
    __nv_bfloat16 h2 = __float2bfloat16(v.z), h3 = __float2bfloat16(v.w);
    hp[i * 2]     = __nv_bfloat162{h0, h1};
    hp[i * 2 + 1] = __nv_bfloat162{h2, h3};
    lp[i * 2]     = __nv_bfloat162{__float2bfloat16(v.x - __bfloat162float(h0)),
                                   __float2bfloat16(v.y - __bfloat162float(h1))};
    lp[i * 2 + 1] = __nv_bfloat162{__float2bfloat16(v.z - __bfloat162float(h2)),
                                   __float2bfloat16(v.w - __bfloat162float(h3))};
}

__global__ void cvt_hilo_kernel(const float* __restrict__ s,
                                __nv_bfloat16* __restrict__ hi,
                                __nv_bfloat16* __restrict__ lo, int n4)
{
    int i = blockIdx.x * 256 + threadIdx.x;
    if (i >= n4) return;
    float4 v = ((const float4*)s)[i];
    cvt_one4(v, (__nv_bfloat162*)hi, (__nv_bfloat162*)lo, i);
}

// all four W_ih matrices in one launch; slot k -> whi/wlo + k*G4*DD
__global__ void cvt_w4_kernel(const float* __restrict__ w0, const float* __restrict__ w1,
                              const float* __restrict__ w2, const float* __restrict__ w3,
                              __nv_bfloat16* __restrict__ hi, __nv_bfloat16* __restrict__ lo)
{
    const int NW4 = G4 * DD / 4;   // 32768 float4 per matrix
    int gid = blockIdx.x * 256 + threadIdx.x;
    if (gid >= 4 * NW4) return;
    int seg = gid / NW4;
    int i = gid - seg * NW4;
    const float* src = (seg == 0) ? w0 : (seg == 1) ? w1 : (seg == 2) ? w2 : w3;
    float4 v = ((const float4*)src)[i];
    __nv_bfloat162* hp = (__nv_bfloat162*)(hi + (size_t)seg * G4 * DD);
    __nv_bfloat162* lp = (__nv_bfloat162*)(lo + (size_t)seg * G4 * DD);
    cvt_one4(v, hp, lp, i);
}

// =====================================================================
// bf16x3 GEMM via mma.sync m16n8k16, 3-stage cp.async pipeline,
// single barrier per chunk, prefetch depth 2. FROZEN (round 11).
// =====================================================================
#define KC    64
#define AROW  72                 // KC + 8 pad (bf16 elems); 144B row (16B-aligned)
#define TILEB (128 * AROW * 2)
#define STAGEB (2 * TILEB)       // 36864
#define NSTAGE 3
#define GEMM_SMEM (NSTAGE * STAGEB)   // 110592

__global__ __launch_bounds__(256, 2)
void gemm_mma_kernel(const __nv_bfloat16* __restrict__ xhi,
                     const __nv_bfloat16* __restrict__ xlo,
                     const __nv_bfloat16* __restrict__ whi,
                     const __nv_bfloat16* __restrict__ wlo,
                     const float* __restrict__ bihf, const float* __restrict__ bhhf,
                     const float* __restrict__ bihb, const float* __restrict__ bhhb,
                     float* __restrict__ gx)
{
    __shared__ float sbias[128];

    const int tid = threadIdx.x;
    const int lane = tid & 31;
    const int wid = tid >> 5;
    const int warp_m = wid >> 2;
    const int warp_n = wid & 3;
    const int m0 = blockIdx.y * 128;
    const int n0 = blockIdx.x * 128;
    const int dir = blockIdx.z;
    const __nv_bfloat16* Wh = whi + (size_t)dir * G4 * DD;
    const __nv_bfloat16* Wl = wlo + (size_t)dir * G4 * DD;
    const float* bih = dir ? bihb : bihf;
    const float* bhh = dir ? bhhb : bhhf;
    const uint32_t sdyn = smem_u32(smem_raw);

    if (tid < 128) sbias[tid] = bih[n0 + tid] + bhh[n0 + tid];

    float acc[4][4][4];
#pragma unroll
    for (int mt = 0; mt < 4; mt++)
#pragma unroll
        for (int nt = 0; nt < 4; nt++)
#pragma unroll
            for (int q = 0; q < 4; q++) acc[mt][nt][q] = 0.0f;

    uint32_t aOff[4], bOff[2];
#pragma unroll
    for (int mt = 0; mt < 4; mt++) {
        int row = warp_m * 64 + mt * 16 + (lane & 15);
        aOff[mt] = (uint32_t)((row * AROW + (lane >> 4) * 8) * 2);
    }
#pragma unroll
    for (int nh = 0; nh < 2; nh++) {
        int row = warp_n * 32 + nh * 16 + (lane & 15);
        bOff[nh] = (uint32_t)(TILEB + (row * AROW + (lane >> 4) * 8) * 2);
    }

    auto prefetch = [&](int c, int st) {
        const __nv_bfloat16* Asrc = (c >= 4 && c < 8) ? xlo : xhi;
        const __nv_bfloat16* Bsrc = (c >= 8) ? Wl : Wh;
        int kc = (c & 3) * KC;
        uint32_t base = sdyn + st * STAGEB;
#pragma unroll
        for (int i = 0; i < 4; i++) {
            int u = tid + i * 256;
            int row = u >> 3;
            int c8 = (u & 7) * 8;
            cpa16(base + (uint32_t)((row * AROW + c8) * 2),
                  Asrc + (size_t)(m0 + row) * DD + kc + c8);
            cpa16(base + (uint32_t)(TILEB + (row * AROW + c8) * 2),
                  Bsrc + (size_t)(n0 + row) * DD + kc + c8);
        }
        asm volatile("cp.async.commit_group;" ::: "memory");
    };

    prefetch(0, 0);
    prefetch(1, 1);
    for (int c = 0; c < 12; c++) {
        if (c < 11) {
            asm volatile("cp.async.wait_group 1;" ::: "memory");
        } else {
            asm volatile("cp.async.wait_group 0;" ::: "memory");
        }
        __syncthreads();   // all warps finished compute(c-1); stage (c+2)%3 free
        if (c + 2 < 12) prefetch(c + 2, (c + 2) % NSTAGE);

        uint32_t st = sdyn + (uint32_t)((c % NSTAGE) * STAGEB);
#pragma unroll
        for (int k16 = 0; k16 < KC / 16; k16++) {
            uint32_t a[4][4], b[2][4];
#pragma unroll
            for (int mt = 0; mt < 4; mt++)
                ldm_x4(a[mt], st + aOff[mt] + k16 * 32);
#pragma unroll
            for (int nh = 0; nh < 2; nh++)
                ldm_x4(b[nh], st + bOff[nh] + k16 * 32);
#pragma unroll
            for (int mt = 0; mt < 4; mt++)
#pragma unroll
                for (int nt = 0; nt < 4; nt++) {
                    int nh = nt >> 1, sub = nt & 1;
                    mma_bf16(acc[mt][nt], a[mt], b[nh][sub], b[nh][sub + 2]);
                }
        }
    }

    float* gxd = gx + (size_t)dir * M_TOTAL * G4;
#pragma unroll
    for (int mt = 0; mt < 4; mt++) {
        int r0 = m0 + warp_m * 64 + mt * 16 + (lane >> 2);
#pragma unroll
        for (int nt = 0; nt < 4; nt++) {
            int cidx = warp_n * 32 + nt * 8 + (lane & 3) * 2;
            int col = n0 + cidx;
            float2 v0 = make_float2(acc[mt][nt][0] + sbias[cidx],
                                    acc[mt][nt][1] + sbias[cidx + 1]);
            float2 v1 = make_float2(acc[mt][nt][2] + sbias[cidx],
                                    acc[mt][nt][3] + sbias[cidx + 1]);
            *(float2*)(gxd + (size_t)r0 * G4 + col) = v0;
            *(float2*)(gxd + (size_t)(r0 + 8) * G4 + col) = v1;
        }
    }
}

// =====================================================================
// LSTM scan (pair-thread; MODE compile-time). KREG 80 / KS 48:
// weight regs 160, total live ~230 -> no spills (was pinned at 254).
// =====================================================================
#define KREG 80
#define KS   48
#define NK4  (KS / 4)  // 12
#define SCAN_SMEM (NK4 * 2 * 256 * 16 + 2 * HH * 4)  // 98304 + 1024

template<int MODE>
__global__ __launch_bounds__(256, 1)
void lstm_scan_kernel(const float* __restrict__ gx,
                      const float* __restrict__ w_hh_f,
                      const float* __restrict__ w_hh_b,
                      float* __restrict__ outF,
                      __nv_bfloat16* __restrict__ outHi,
                      __nv_bfloat16* __restrict__ outLo)
{
    float* smem = (float*)smem_raw;
    const int bid = blockIdx.x;     // 0..127
    const int dir = bid >> 6;
    const int b   = bid & 63;
    const int j   = threadIdx.x;    // 0..255
    const int odd = j & 1;
    const int unit = j >> 1;        // 0..127
    const int row0 = unit + (odd << 7);   // i or f
    const int row1 = row0 + 256;          // g or o
    const float* W = dir ? w_hh_b : w_hh_f;

    ulonglong2* ws2 = (ulonglong2*)smem;            // [NK4][2][256]
    float* shb = smem + NK4 * 2 * 256 * 4;          // h double buffer [2][128]

    u64 wr0[KREG / 2], wr1[KREG / 2];
    {
        const u64* wp0 = (const u64*)(W + (size_t)row0 * HH);
        const u64* wp1 = (const u64*)(W + (size_t)row1 * HH);
#pragma unroll
        for (int p = 0; p < KREG / 2; p++) { wr0[p] = wp0[p]; wr1[p] = wp1[p]; }
    }
#pragma unroll
    for (int k4 = 0; k4 < NK4; k4++) {
        ws2[(k4 * 2 + 0) * 256 + j] = *(const ulonglong2*)(W + (size_t)row0 * HH + KREG + k4 * 4);
        ws2[(k4 * 2 + 1) * 256 + j] = *(const ulonglong2*)(W + (size_t)row1 * HH + KREG + k4 * 4);
    }
    if (j < HH) shb[j] = 0.0f;      // h_{-1} = 0 in buffer 0
    float c = 0.0f;
    __syncthreads();

    const float* gxb = gx + ((size_t)dir * BB + b) * TT * G4;
    const int dt = dir ? -1 : 1;
    int tt = dir ? (TT - 1) : 0;
    float g0 = gxb[(size_t)tt * G4 + row0];
    float g1 = gxb[(size_t)tt * G4 + row1];

    for (int t = 0; t < TT; t++) {
        int ttn = tt + dt;
        float gn0 = 0.f, gn1 = 0.f;
        if (t < TT - 1) {
            gn0 = gxb[(size_t)ttn * G4 + row0];
            gn1 = gxb[(size_t)ttn * G4 + row1];
        }

        const float* sh = shb + ((t & 1) << 7);        // read h_{t-1}
        float* shw = shb + (((t + 1) & 1) << 7);       // write h_t

        u64 a0a = 0ull, a0b = 0ull, a1a = 0ull, a1b = 0ull;
#pragma unroll
        for (int p = 0; p < KREG / 2; p += 2) {
            ulonglong2 h2 = *(const ulonglong2*)(sh + p * 2);
            fma2(a0a, wr0[p],     h2.x);
            fma2(a0b, wr0[p + 1], h2.y);
            fma2(a1a, wr1[p],     h2.x);
            fma2(a1b, wr1[p + 1], h2.y);
        }
#pragma unroll
        for (int k4 = 0; k4 < NK4; k4++) {
            ulonglong2 h2 = *(const ulonglong2*)(sh + KREG + k4 * 4);
            ulonglong2 w0 = ws2[(k4 * 2 + 0) * 256 + j];
            fma2(a0a, w0.x, h2.x);
            fma2(a0b, w0.y, h2.y);
            ulonglong2 w1 = ws2[(k4 * 2 + 1) * 256 + j];
            fma2(a1a, w1.x, h2.x);
            fma2(a1b, w1.y, h2.y);
        }
        u64 s0, s1;
        add2(s0, a0a, a0b);
        add2(s1, a1a, a1b);
        float2 v0 = unpk(s0), v1 = unpk(s1);
        float a0 = g0 + v0.x + v0.y;   // i or f pre-activation
        float a1 = g1 + v1.x + v1.y;   // g or o pre-activation

        float p0 = fsig(a0);
        float scale = odd ? 1.0f : 2.0f;
        float s = fsig(a1 * scale);
        float p1 = odd ? s : fmaf(2.0f, s, -1.0f);

        float q0 = __shfl_xor_sync(0xffffffffu, p0, 1);  // even gets f
        float q1 = __shfl_xor_sync(0xffffffffu, p1, 1);  // even gets o

        if (!odd) {
            c = q0 * c + p0 * p1;            // f*c + i*g
            float h = q1 * ftanh_id(c);      // o*tanh(c)
            shw[unit] = h;
            size_t oidx = ((size_t)b * TT + tt) * DD + dir * HH + unit;
            if (MODE == 0) {
                __nv_bfloat16 hh = __float2bfloat16(h);
                outHi[oidx] = hh;
                outLo[oidx] = __float2bfloat16(h - __bfloat162float(hh));
            } else {
                outF[oidx] = h;
            }
        }
        __syncthreads();

        g0 = gn0; g1 = gn1;
        tt = ttn;
    }
}

// =====================================================================
// Emissions: one warp per row.
// =====================================================================
__global__ void emissions_kernel(const float* __restrict__ seq,
                                 const float* __restrict__ fcw,
                                 const float* __restrict__ fcb,
                                 float* __restrict__ em)
{
    int gw = (int)((blockIdx.x * blockDim.x + threadIdx.x) >> 5);
    int lane = threadIdx.x & 31;
    if (gw >= M_TOTAL) return;
    const float* row = seq + (size_t)gw * 256 + lane * 8;
    float4 xa = *(const float4*)(row);
    float4 xb = *(const float4*)(row + 4);
#pragma unroll
    for (int tag = 0; tag < NTAGS; tag++) {
        const float* w = fcw + tag * 256 + lane * 8;
        float4 wa = *(const float4*)(w);
        float4 wb = *(const float4*)(w + 4);
        float p = xa.x * wa.x + xa.y * wa.y + xa.z * wa.z + xa.w * wa.w
                + xb.x * wb.x + xb.y * wb.y + xb.z * wb.z + xb.w * wb.w;
#pragma unroll
        for (int off = 16; off > 0; off >>= 1)
            p += __shfl_xor_sync(0xffffffffu, p, off);
        if (lane == 0) em[(size_t)gw * NTAGS + tag] = p + fcb[tag];
    }
}

// =====================================================================
// CRF: smem-staged emissions + tags, fast exp / accurate log DP.
// =====================================================================
__global__ __launch_bounds__(128)
void crf_batch_kernel(const float* __restrict__ em,
                      const int* __restrict__ tags,
                      const float* __restrict__ startv,
                      const float* __restrict__ endv,
                      const float* __restrict__ trans,
                      float* __restrict__ part)
{
    __shared__ float sem[TT * NTAGS];   // 12 KB
    __shared__ int   stg[TT];           // 4 KB
    __shared__ float sred[4];

    const int b = blockIdx.x;
    const int tid = threadIdx.x;
    const int lane = tid & 31;
    const int wid = tid >> 5;
    const float* emb = em + (size_t)b * TT * NTAGS;
    const int* tg = tags + (size_t)b * TT;

    for (int i = tid; i < TT * NTAGS; i += 128) sem[i] = emb[i];
    for (int i = tid; i < TT; i += 128) stg[i] = tg[i];
    __syncthreads();

    float s = 0.0f;
    for (int t = tid; t < TT; t += 128) {
        int tag = stg[t];
        s += sem[t * NTAGS + tag];
        if (t > 0) s += trans[stg[t - 1] * NTAGS + tag];
    }
#pragma unroll
    for (int off = 16; off > 0; off >>= 1)
        s += __shfl_xor_sync(0xffffffffu, s, off);
    if (lane == 0) sred[wid] = s;
    __syncthreads();

    if (wid == 0) {
        float alpha = -1e30f;
        float tr0 = 0.f, tr1 = 0.f, tr2 = 0.f, endl = 0.f;
        if (lane < NTAGS) {
            alpha = startv[lane] + sem[lane];
            tr0 = trans[0 * NTAGS + lane];
            tr1 = trans[1 * NTAGS + lane];
            tr2 = trans[2 * NTAGS + lane];
            endl = endv[lane];
        }
        for (int t = 1; t < TT; t++) {
            float a0 = __shfl_sync(0xffffffffu, alpha, 0);
            float a1 = __shfl_sync(0xffffffffu, alpha, 1);
            float a2 = __shfl_sync(0xffffffffu, alpha, 2);
            if (lane < NTAGS) {
                float v0 = a0 + tr0, v1 = a1 + tr1, v2 = a2 + tr2;
                float m = fmaxf(v0, fmaxf(v1, v2));
                alpha = sem[t * NTAGS + lane] + m +
                        logf(__expf(v0 - m) + __expf(v1 - m) + __expf(v2 - m));
            }
        }
        if (lane < NTAGS) alpha += endl;
        float a0 = __shfl_sync(0xffffffffu, alpha, 0);
        float a1 = __shfl_sync(0xffffffffu, alpha, 1);
        float a2 = __shfl_sync(0xffffffffu, alpha, 2);
        if (lane == 0) {
            float m = fmaxf(a0, fmaxf(a1, a2));
            float logZ = m + logf(__expf(a0 - m) + __expf(a1 - m) + __expf(a2 - m));
            float stotal = sred[0] + sred[1] + sred[2] + sred[3];
            float num = stotal + startv[stg[0]] + endv[stg[TT - 1]];
            part[b] = num - logZ;
        }
    }
}

__global__ void crf_reduce_kernel(const float* __restrict__ part, float* __restrict__ out)
{
    float s = 0.0f;
    for (int i = 0; i < BB; i++) s += part[i];
    out[0] = -s / (float)BB;
}

// =====================================================================
extern "C" void kernel_launch(void* const* d_in, const int* in_sizes, int n_in,
                              void* d_out, int out_size)
{
    const float* x         = (const float*)d_in[0];
    const int*   tags      = (const int*)  d_in[1];
    const float* w_ih_l0   = (const float*)d_in[2];
    const float* w_hh_l0   = (const float*)d_in[3];
    const float* b_ih_l0   = (const float*)d_in[4];
    const float* b_hh_l0   = (const float*)d_in[5];
    const float* w_ih_l0r  = (const float*)d_in[6];
    const float* w_hh_l0r  = (const float*)d_in[7];
    const float* b_ih_l0r  = (const float*)d_in[8];
    const float* b_hh_l0r  = (const float*)d_in[9];
    const float* w_ih_l1   = (const float*)d_in[10];
    const float* w_hh_l1   = (const float*)d_in[11];
    const float* b_ih_l1   = (const float*)d_in[12];
    const float* b_hh_l1   = (const float*)d_in[13];
    const float* w_ih_l1r  = (const float*)d_in[14];
    const float* w_hh_l1r  = (const float*)d_in[15];
    const float* b_ih_l1r  = (const float*)d_in[16];
    const float* b_hh_l1r  = (const float*)d_in[17];
    const float* fc_w      = (const float*)d_in[18];
    const float* fc_b      = (const float*)d_in[19];
    const float* crf_start = (const float*)d_in[20];
    const float* crf_end   = (const float*)d_in[21];
    const float* crf_trans = (const float*)d_in[22];

    float* out = (float*)d_out;

    float *gx, *seq1, *part;
    __nv_bfloat16 *xhi, *xlo, *whi, *wlo;
    cudaGetSymbolAddress((void**)&gx,   g_gx);
    cudaGetSymbolAddress((void**)&seq1, g_seq1);
    cudaGetSymbolAddress((void**)&part, g_part);
    cudaGetSymbolAddress((void**)&xhi,  g_xhi);
    cudaGetSymbolAddress((void**)&xlo,  g_xlo);
    cudaGetSymbolAddress((void**)&whi,  g_whi);
    cudaGetSymbolAddress((void**)&wlo,  g_wlo);

    cudaFuncSetAttribute(lstm_scan_kernel<0>,
                         cudaFuncAttributeMaxDynamicSharedMemorySize, SCAN_SMEM);
    cudaFuncSetAttribute(lstm_scan_kernel<1>,
                         cudaFuncAttributeMaxDynamicSharedMemorySize, SCAN_SMEM);
    cudaFuncSetAttribute(gemm_mma_kernel,
                         cudaFuncAttributeMaxDynamicSharedMemorySize, GEMM_SMEM);

    const int NX4 = M_TOTAL * DD / 4;
    const int NWALL = 4 * (G4 * DD / 4);
    dim3 ggrid(4, 512, 2);
    const size_t WSET = (size_t)G4 * DD;

    // ---- all conversions up front ----
    cvt_hilo_kernel<<<(NX4 + 255) / 256, 256>>>(x, xhi, xlo, NX4);
    cvt_w4_kernel<<<(NWALL + 255) / 256, 256>>>(w_ih_l0, w_ih_l0r, w_ih_l1, w_ih_l1r,
                                                whi, wlo);

    // ---- layer 0 (weight slots 0,1) ----
    gemm_mma_kernel<<<ggrid, 256, GEMM_SMEM>>>(xhi, xlo, whi, wlo,
                                               b_ih_l0, b_hh_l0, b_ih_l0r, b_hh_l0r, gx);
    lstm_scan_kernel<0><<<128, 256, SCAN_SMEM>>>(gx, w_hh_l0, w_hh_l0r,
                                                 (float*)nullptr, xhi, xlo);

    // ---- layer 1 (weight slots 2,3) ----
    gemm_mma_kernel<<<ggrid, 256, GEMM_SMEM>>>(xhi, xlo, whi + 2 * WSET, wlo + 2 * WSET,
                                               b_ih_l1, b_hh_l1, b_ih_l1r, b_hh_l1r, gx);
    lstm_scan_kernel<1><<<128, 256, SCAN_SMEM>>>(gx, w_hh_l1, w_hh_l1r,
                                                 seq1, (__nv_bfloat16*)nullptr,
                                                 (__nv_bfloat16*)nullptr);

    // ---- emissions + CRF ----
    emissions_kernel<<<(M_TOTAL * 32 + 255) / 256, 256>>>(seq1, fc_w, fc_b, out + 1);
    crf_batch_kernel<<<BB, 128>>>(out + 1, tags, crf_start, crf_end, crf_trans, part);
    crf_reduce_kernel<<<1, 1>>>(part, out);
}

// round 13
// speedup vs baseline: 1.0169x; 1.0169x over previous
#include <cuda_runtime.h>
#include <cuda_bf16.h>
#include <math.h>
#include <cstdint>

#define BB 64
#define TT 1024
#define DD 256
#define HH 128
#define G4 512           // 4*H gate width
#define NTAGS 3
#define M_TOTAL (BB*TT)  // 65536

typedef unsigned long long u64;

// single dynamic-shared extern for all kernels
extern __shared__ char smem_raw[];

// ---------------- static scratch (no allocs allowed) ----------------
__device__ float g_gx[(size_t)2 * BB * TT * G4];        // [dir][b][t][512]
__device__ float g_seq1[(size_t)BB * TT * 2 * HH];      // layer1 output (fp32)
__device__ float g_part[BB];
__device__ __nv_bfloat16 g_xhi[(size_t)M_TOTAL * DD];   // A hi
__device__ __nv_bfloat16 g_xlo[(size_t)M_TOTAL * DD];   // A lo
__device__ __nv_bfloat16 g_whi[(size_t)4 * G4 * DD];    // W hi (l0,l0r,l1,l1r)
__device__ __nv_bfloat16 g_wlo[(size_t)4 * G4 * DD];    // W lo

// fast sigmoid / tanh (err ~2^-20)
__device__ __forceinline__ float fsig(float x) {
    return __fdividef(1.0f, 1.0f + __expf(-x));
}
__device__ __forceinline__ float ftanh_id(float x) {   // 2*sig(2x)-1
    return fmaf(2.0f, __fdividef(1.0f, 1.0f + __expf(-2.0f * x)), -1.0f);
}

// ---- packed f32x2 helpers ----
__device__ __forceinline__ void fma2(u64& d, u64 a, u64 b) {
    asm("fma.rn.f32x2 %0, %1, %2, %0;" : "+l"(d) : "l"(a), "l"(b));
}
__device__ __forceinline__ void add2(u64& d, u64 a, u64 b) {
    asm("add.rn.f32x2 %0, %1, %2;" : "=l"(d) : "l"(a), "l"(b));
}
__device__ __forceinline__ float2 unpk(u64 v) {
    float2 f; asm("mov.b64 {%0, %1}, %2;" : "=f"(f.x), "=f"(f.y) : "l"(v)); return f;
}

__device__ __forceinline__ uint32_t smem_u32(const void* p) {
    uint32_t a;
    asm("{ .reg .u64 t; cvta.to.shared.u64 t, %1; cvt.u32.u64 %0, t; }" : "=r"(a) : "l"(p));
    return a;
}

// ---- ldmatrix / mma.sync / cp.async (base sm_80+ ISA) ----
__device__ __forceinline__ void ldm_x4(uint32_t* r, uint32_t addr) {
    asm volatile("ldmatrix.sync.aligned.m8n8.x4.shared.b16 {%0,%1,%2,%3}, [%4];"
        : "=r"(r[0]), "=r"(r[1]), "=r"(r[2]), "=r"(r[3]) : "r"(addr));
}
__device__ __forceinline__ void mma_bf16(float* d, const uint32_t* a, uint32_t b0, uint32_t b1) {
    asm volatile("mma.sync.aligned.m16n8k16.row.col.f32.bf16.bf16.f32 "
        "{%0,%1,%2,%3}, {%4,%5,%6,%7}, {%8,%9}, {%0,%1,%2,%3};"
        : "+f"(d[0]), "+f"(d[1]), "+f"(d[2]), "+f"(d[3])
        : "r"(a[0]), "r"(a[1]), "r"(a[2]), "r"(a[3]), "r"(b0), "r"(b1));
}
__device__ __forceinline__ void cpa16(uint32_t dst, const void* src) {
    asm volatile("cp.async.cg.shared.global [%0], [%1], 16;" :: "r"(dst), "l"(src));
}

// =====================================================================
// fp32 -> bf16 hi/lo split (vectorized x4)
// =====================================================================
__device__ __forceinline__ void cvt_one4(const float4& v,
                                         __nv_bfloat162* hp, __nv_bfloat162* lp, int i)
{
    __nv_bfloat16 h0 = __float2bfloat16(v.x), h1 = __float2bfloat16(v.y);
    __nv_bfloat16 h2 = __float2bfloat16(v.z), h3 = __float2bfloat16(v.w);
    hp[i * 2]     = __nv_bfloat162{h0, h1};
    hp[i * 2 + 1] = __nv_bfloat162{h2, h3};
    lp[i * 2]     = __nv_bfloat162{__float2bfloat16(v.x - __bfloat162float(h0)),
                                   __float2bfloat16(v.y - __bfloat162float(h1))};
    lp[i * 2 + 1] = __nv_bfloat162{__float2bfloat16(v.z - __bfloat162float(h2)),
                                   __float2bfloat16(v.w - __bfloat162float(h3))};
}

__global__ void cvt_hilo_kernel(const float* __restrict__ s,
                                __nv_bfloat16* __restrict__ hi,
                                __nv_bfloat16* __restrict__ lo, int n4)
{
    int i = blockIdx.x * 256 + threadIdx.x;
    if (i >= n4) return;
    float4 v = ((const float4*)s)[i];
    cvt_one4(v, (__nv_bfloat162*)hi, (__nv_bfloat162*)lo, i);
}

// all four W_ih matrices in one launch; slot k -> whi/wlo + k*G4*DD
__global__ void cvt_w4_kernel(const float* __restrict__ w0, const float* __restrict__ w1,
                              const float* __restrict__ w2, const float* __restrict__ w3,
                              __nv_bfloat16* __restrict__ hi, __nv_bfloat16* __restrict__ lo)
{
    const int NW4 = G4 * DD / 4;   // 32768 float4 per matrix
    int gid = blockIdx.x * 256 + threadIdx.x;
    if (gid >= 4 * NW4) return;
    int seg = gid / NW4;
    int i = gid - seg * NW4;
    const float* src = (seg == 0) ? w0 : (seg == 1) ? w1 : (seg == 2) ? w2 : w3;
    float4 v = ((const float4*)src)[i];
    __nv_bfloat162* hp = (__nv_bfloat162*)(hi + (size_t)seg * G4 * DD);
    __nv_bfloat162* lp = (__nv_bfloat162*)(lo + (size_t)seg * G4 * DD);
    cvt_one4(v, hp, lp, i);
}

// =====================================================================
// bf16x3 GEMM via mma.sync m16n8k16.
// NEW: per kc-chunk load ALL FOUR tiles (Ahi, Alo, Whi, Wlo) once and
// run the 3 passes (Ahi*Wh, Alo*Wh, Ahi*Wl) from smem.
// Global traffic: 256KB/block (was 384KB). 2-stage pipeline.
// =====================================================================
#define KC    64
#define AROW  72                 // KC + 8 pad (bf16 elems); 144B row
#define TILEB (128 * AROW * 2)   // 18432 bytes
#define STAGEB (4 * TILEB)       // 73728 per stage (Ahi, Alo, Wh, Wl)
#define GEMM_SMEM (2 * STAGEB)   // 147456

__global__ __launch_bounds__(256, 1)
void gemm_mma_kernel(const __nv_bfloat16* __restrict__ xhi,
                     const __nv_bfloat16* __restrict__ xlo,
                     const __nv_bfloat16* __restrict__ whi,
                     const __nv_bfloat16* __restrict__ wlo,
                     const float* __restrict__ bihf, const float* __restrict__ bhhf,
                     const float* __restrict__ bihb, const float* __restrict__ bhhb,
                     float* __restrict__ gx)
{
    __shared__ float sbias[128];

    const int tid = threadIdx.x;
    const int lane = tid & 31;
    const int wid = tid >> 5;
    const int warp_m = wid >> 2;
    const int warp_n = wid & 3;
    const int m0 = blockIdx.y * 128;
    const int n0 = blockIdx.x * 128;
    const int dir = blockIdx.z;
    const __nv_bfloat16* Wh = whi + (size_t)dir * G4 * DD;
    const __nv_bfloat16* Wl = wlo + (size_t)dir * G4 * DD;
    const float* bih = dir ? bihb : bihf;
    const float* bhh = dir ? bhhb : bhhf;
    const uint32_t sdyn = smem_u32(smem_raw);

    if (tid < 128) sbias[tid] = bih[n0 + tid] + bhh[n0 + tid];

    float acc[4][4][4];
#pragma unroll
    for (int mt = 0; mt < 4; mt++)
#pragma unroll
        for (int nt = 0; nt < 4; nt++)
#pragma unroll
            for (int q = 0; q < 4; q++) acc[mt][nt][q] = 0.0f;

    // tile-relative ldmatrix byte offsets
    uint32_t aOff[4], bOff[2];
#pragma unroll
    for (int mt = 0; mt < 4; mt++) {
        int row = warp_m * 64 + mt * 16 + (lane & 15);
        aOff[mt] = (uint32_t)((row * AROW + (lane >> 4) * 8) * 2);
    }
#pragma unroll
    for (int nh = 0; nh < 2; nh++) {
        int row = warp_n * 32 + nh * 16 + (lane & 15);
        bOff[nh] = (uint32_t)((row * AROW + (lane >> 4) * 8) * 2);
    }

    // prefetch one kc chunk: all 4 tiles
    auto prefetch = [&](int c, int st) {
        int kc = c * KC;
        uint32_t base = sdyn + st * STAGEB;
#pragma unroll
        for (int i = 0; i < 4; i++) {
            int u = tid + i * 256;     // 0..1023
            int row = u >> 3;          // 0..127
            int c8 = (u & 7) * 8;      // 0..56
            uint32_t o = (uint32_t)((row * AROW + c8) * 2);
            cpa16(base + o,             xhi + (size_t)(m0 + row) * DD + kc + c8);
            cpa16(base + TILEB + o,     xlo + (size_t)(m0 + row) * DD + kc + c8);
            cpa16(base + 2 * TILEB + o, Wh  + (size_t)(n0 + row) * DD + kc + c8);
            cpa16(base + 3 * TILEB + o, Wl  + (size_t)(n0 + row) * DD + kc + c8);
        }
        asm volatile("cp.async.commit_group;" ::: "memory");
    };

    prefetch(0, 0);
    for (int c = 0; c < 4; c++) {
        if (c + 1 < 4) {
            prefetch(c + 1, (c + 1) & 1);
            asm volatile("cp.async.wait_group 1;" ::: "memory");
        } else {
            asm volatile("cp.async.wait_group 0;" ::: "memory");
        }
        __syncthreads();

        uint32_t st = sdyn + (uint32_t)((c & 1) * STAGEB);
        // passes: (Ahi,Wh), (Alo,Wh), (Ahi,Wl)
#pragma unroll
        for (int pass = 0; pass < 3; pass++) {
            uint32_t aBase = st + ((pass == 1) ? TILEB : 0u);
            uint32_t bBase = st + ((pass == 2) ? 3u * TILEB : 2u * TILEB);
#pragma unroll
            for (int k16 = 0; k16 < KC / 16; k16++) {
                uint32_t a[4][4], b[2][4];
#pragma unroll
                for (int mt = 0; mt < 4; mt++)
                    ldm_x4(a[mt], aBase + aOff[mt] + k16 * 32);
#pragma unroll
                for (int nh = 0; nh < 2; nh++)
                    ldm_x4(b[nh], bBase + bOff[nh] + k16 * 32);
#pragma unroll
                for (int mt = 0; mt < 4; mt++)
#pragma unroll
                    for (int nt = 0; nt < 4; nt++) {
                        int nh = nt >> 1, sub = nt & 1;
                        mma_bf16(acc[mt][nt], a[mt], b[nh][sub], b[nh][sub + 2]);
                    }
            }
        }
        __syncthreads();
    }

    float* gxd = gx + (size_t)dir * M_TOTAL * G4;
#pragma unroll
    for (int mt = 0; mt < 4; mt++) {
        int r0 = m0 + warp_m * 64 + mt * 16 + (lane >> 2);
#pragma unroll
        for (int nt = 0; nt < 4; nt++) {
            int cidx = warp_n * 32 + nt * 8 + (lane & 3) * 2;
            int col = n0 + cidx;
            float2 v0 = make_float2(acc[mt][nt][0] + sbias[cidx],
                                    acc[mt][nt][1] + sbias[cidx + 1]);
            float2 v1 = make_float2(acc[mt][nt][2] + sbias[cidx],
                                    acc[mt][nt][3] + sbias[cidx + 1]);
            *(float2*)(gxd + (size_t)r0 * G4 + col) = v0;
            *(float2*)(gxd + (size_t)(r0 + 8) * G4 + col) = v1;
        }
    }
}

// =====================================================================
// LSTM scan (pair-thread; MODE compile-time). KREG 88 / KS 40 —
// measured optimum (round 11: 807us/layer).
// =====================================================================
#define KREG 88
#define KS   40
#define NK4  (KS / 4)  // 10
#define SCAN_SMEM (NK4 * 2 * 256 * 16 + 2 * HH * 4)  // 81920 + 1024

template<int MODE>
__global__ __launch_bounds__(256, 1)
void lstm_scan_kernel(const float* __restrict__ gx,
                      const float* __restrict__ w_hh_f,
                      const float* __restrict__ w_hh_b,
                      float* __restrict__ outF,
                      __nv_bfloat16* __restrict__ outHi,
                      __nv_bfloat16* __restrict__ outLo)
{
    float* smem = (float*)smem_raw;
    const int bid = blockIdx.x;     // 0..127
    const int dir = bid >> 6;
    const int b   = bid & 63;
    const int j   = threadIdx.x;    // 0..255
    const int odd = j & 1;
    const int unit = j >> 1;        // 0..127
    const int row0 = unit + (odd << 7);   // i or f
    const int row1 = row0 + 256;          // g or o
    const float* W = dir ? w_hh_b : w_hh_f;

    ulonglong2* ws2 = (ulonglong2*)smem;            // [NK4][2][256]
    float* shb = smem + NK4 * 2 * 256 * 4;          // h double buffer [2][128]

    u64 wr0[KREG / 2], wr1[KREG / 2];
    {
        const u64* wp0 = (const u64*)(W + (size_t)row0 * HH);
        const u64* wp1 = (const u64*)(W + (size_t)row1 * HH);
#pragma unroll
        for (int p = 0; p < KREG / 2; p++) { wr0[p] = wp0[p]; wr1[p] = wp1[p]; }
    }
#pragma unroll
    for (int k4 = 0; k4 < NK4; k4++) {
        ws2[(k4 * 2 + 0) * 256 + j] = *(const ulonglong2*)(W + (size_t)row0 * HH + KREG + k4 * 4);
        ws2[(k4 * 2 + 1) * 256 + j] = *(const ulonglong2*)(W + (size_t)row1 * HH + KREG + k4 * 4);
    }
    if (j < HH) shb[j] = 0.0f;      // h_{-1} = 0 in buffer 0
    float c = 0.0f;
    __syncthreads();

    const float* gxb = gx + ((size_t)dir * BB + b) * TT * G4;
    const int dt = dir ? -1 : 1;
    int tt = dir ? (TT - 1) : 0;
    float g0 = gxb[(size_t)tt * G4 + row0];
    float g1 = gxb[(size_t)tt * G4 + row1];

    for (int t = 0; t < TT; t++) {
        int ttn = tt + dt;
        float gn0 = 0.f, gn1 = 0.f;
        if (t < TT - 1) {
            gn0 = gxb[(size_t)ttn * G4 + row0];
            gn1 = gxb[(size_t)ttn * G4 + row1];
        }

        const float* sh = shb + ((t & 1) << 7);        // read h_{t-1}
        float* shw = shb + (((t + 1) & 1) << 7);       // write h_t

        u64 a0a = 0ull, a0b = 0ull, a1a = 0ull, a1b = 0ull;
#pragma unroll
        for (int p = 0; p < KREG / 2; p += 2) {
            ulonglong2 h2 = *(const ulonglong2*)(sh + p * 2);
            fma2(a0a, wr0[p],     h2.x);
            fma2(a0b, wr0[p + 1], h2.y);
            fma2(a1a, wr1[p],     h2.x);
            fma2(a1b, wr1[p + 1], h2.y);
        }
#pragma unroll
        for (int k4 = 0; k4 < NK4; k4++) {
            ulonglong2 h2 = *(const ulonglong2*)(sh + KREG + k4 * 4);
            ulonglong2 w0 = ws2[(k4 * 2 + 0) * 256 + j];
            fma2(a0a, w0.x, h2.x);
            fma2(a0b, w0.y, h2.y);
            ulonglong2 w1 = ws2[(k4 * 2 + 1) * 256 + j];
            fma2(a1a, w1.x, h2.x);
            fma2(a1b, w1.y, h2.y);
        }
        u64 s0, s1;
        add2(s0, a0a, a0b);
        add2(s1, a1a, a1b);
        float2 v0 = unpk(s0), v1 = unpk(s1);
        float a0 = g0 + v0.x + v0.y;   // i or f pre-activation
        float a1 = g1 + v1.x + v1.y;   // g or o pre-activation

        float p0 = fsig(a0);
        float scale = odd ? 1.0f : 2.0f;
        float s = fsig(a1 * scale);
        float p1 = odd ? s : fmaf(2.0f, s, -1.0f);

        float q0 = __shfl_xor_sync(0xffffffffu, p0, 1);  // even gets f
        float q1 = __shfl_xor_sync(0xffffffffu, p1, 1);  // even gets o

        if (!odd) {
            c = q0 * c + p0 * p1;            // f*c + i*g
            float h = q1 * ftanh_id(c);      // o*tanh(c)
            shw[unit] = h;
            size_t oidx = ((size_t)b * TT + tt) * DD + dir * HH + unit;
            if (MODE == 0) {
                __nv_bfloat16 hh = __float2bfloat16(h);
                outHi[oidx] = hh;
                outLo[oidx] = __float2bfloat16(h - __bfloat162float(hh));
            } else {
                outF[oidx] = h;
            }
        }
        __syncthreads();

        g0 = gn0; g1 = gn1;
        tt = ttn;
    }
}

// =====================================================================
// Emissions: one warp per row.
// =====================================================================
__global__ void emissions_kernel(const float* __restrict__ seq,
                                 const float* __restrict__ fcw,
                                 const float* __restrict__ fcb,
                                 float* __restrict__ em)
{
    int gw = (int)((blockIdx.x * blockDim.x + threadIdx.x) >> 5);
    int lane = threadIdx.x & 31;
    if (gw >= M_TOTAL) return;
    const float* row = seq + (size_t)gw * 256 + lane * 8;
    float4 xa = *(const float4*)(row);
    float4 xb = *(const float4*)(row + 4);
#pragma unroll
    for (int tag = 0; tag < NTAGS; tag++) {
        const float* w = fcw + tag * 256 + lane * 8;
        float4 wa = *(const float4*)(w);
        float4 wb = *(const float4*)(w + 4);
        float p = xa.x * wa.x + xa.y * wa.y + xa.z * wa.z + xa.w * wa.w
                + xb.x * wb.x + xb.y * wb.y + xb.z * wb.z + xb.w * wb.w;
#pragma unroll
        for (int off = 16; off > 0; off >>= 1)
            p += __shfl_xor_sync(0xffffffffu, p, off);
        if (lane == 0) em[(size_t)gw * NTAGS + tag] = p + fcb[tag];
    }
}

// =====================================================================
// CRF: smem-staged emissions + tags, fast exp / accurate log DP.
// =====================================================================
__global__ __launch_bounds__(128)
void crf_batch_kernel(const float* __restrict__ em,
                      const int* __restrict__ tags,
                      const float* __restrict__ startv,
                      const float* __restrict__ endv,
                      const float* __restrict__ trans,
                      float* __restrict__ part)
{
    __shared__ float sem[TT * NTAGS];   // 12 KB
    __shared__ int   stg[TT];           // 4 KB
    __shared__ float sred[4];

    const int b = blockIdx.x;
    const int tid = threadIdx.x;
    const int lane = tid & 31;
    const int wid = tid >> 5;
    const float* emb = em + (size_t)b * TT * NTAGS;
    const int* tg = tags + (size_t)b * TT;

    for (int i = tid; i < TT * NTAGS; i += 128) sem[i] = emb[i];
    for (int i = tid; i < TT; i += 128) stg[i] = tg[i];
    __syncthreads();

    float s = 0.0f;
    for (int t = tid; t < TT; t += 128) {
        int tag = stg[t];
        s += sem[t * NTAGS + tag];
        if (t > 0) s += trans[stg[t - 1] * NTAGS + tag];
    }
#pragma unroll
    for (int off = 16; off > 0; off >>= 1)
        s += __shfl_xor_sync(0xffffffffu, s, off);
    if (lane == 0) sred[wid] = s;
    __syncthreads();

    if (wid == 0) {
        float alpha = -1e30f;
        float tr0 = 0.f, tr1 = 0.f, tr2 = 0.f, endl = 0.f;
        if (lane < NTAGS) {
            alpha = startv[lane] + sem[lane];
            tr0 = trans[0 * NTAGS + lane];
            tr1 = trans[1 * NTAGS + lane];
            tr2 = trans[2 * NTAGS + lane];
            endl = endv[lane];
        }
        for (int t = 1; t < TT; t++) {
            float a0 = __shfl_sync(0xffffffffu, alpha, 0);
            float a1 = __shfl_sync(0xffffffffu, alpha, 1);
            float a2 = __shfl_sync(0xffffffffu, alpha, 2);
            if (lane < NTAGS) {
                float v0 = a0 + tr0, v1 = a1 + tr1, v2 = a2 + tr2;
                float m = fmaxf(v0, fmaxf(v1, v2));
                alpha = sem[t * NTAGS + lane] + m +
                        logf(__expf(v0 - m) + __expf(v1 - m) + __expf(v2 - m));
            }
        }
        if (lane < NTAGS) alpha += endl;
        float a0 = __shfl_sync(0xffffffffu, alpha, 0);
        float a1 = __shfl_sync(0xffffffffu, alpha, 1);
        float a2 = __shfl_sync(0xffffffffu, alpha, 2);
        if (lane == 0) {
            float m = fmaxf(a0, fmaxf(a1, a2));
            float logZ = m + logf(__expf(a0 - m) + __expf(a1 - m) + __expf(a2 - m));
            float stotal = sred[0] + sred[1] + sred[2] + sred[3];
            float num = stotal + startv[stg[0]] + endv[stg[TT - 1]];
            part[b] = num - logZ;
        }
    }
}

__global__ void crf_reduce_kernel(const float* __restrict__ part, float* __restrict__ out)
{
    float s = 0.0f;
    for (int i = 0; i < BB; i++) s += part[i];
    out[0] = -s / (float)BB;
}

// =====================================================================
extern "C" void kernel_launch(void* const* d_in, const int* in_sizes, int n_in,
                              void* d_out, int out_size)
{
    const float* x         = (const float*)d_in[0];
    const int*   tags      = (const int*)  d_in[1];
    const float* w_ih_l0   = (const float*)d_in[2];
    const float* w_hh_l0   = (const float*)d_in[3];
    const float* b_ih_l0   = (const float*)d_in[4];
    const float* b_hh_l0   = (const float*)d_in[5];
    const float* w_ih_l0r  = (const float*)d_in[6];
    const float* w_hh_l0r  = (const float*)d_in[7];
    const float* b_ih_l0r  = (const float*)d_in[8];
    const float* b_hh_l0r  = (const float*)d_in[9];
    const float* w_ih_l1   = (const float*)d_in[10];
    const float* w_hh_l1   = (const float*)d_in[11];
    const float* b_ih_l1   = (const float*)d_in[12];
    const float* b_hh_l1   = (const float*)d_in[13];
    const float* w_ih_l1r  = (const float*)d_in[14];
    const float* w_hh_l1r  = (const float*)d_in[15];
    const float* b_ih_l1r  = (const float*)d_in[16];
    const float* b_hh_l1r  = (const float*)d_in[17];
    const float* fc_w      = (const float*)d_in[18];
    const float* fc_b      = (const float*)d_in[19];
    const float* crf_start = (const float*)d_in[20];
    const float* crf_end   = (const float*)d_in[21];
    const float* crf_trans = (const float*)d_in[22];

    float* out = (float*)d_out;

    float *gx, *seq1, *part;
    __nv_bfloat16 *xhi, *xlo, *whi, *wlo;
    cudaGetSymbolAddress((void**)&gx,   g_gx);
    cudaGetSymbolAddress((void**)&seq1, g_seq1);
    cudaGetSymbolAddress((void**)&part, g_part);
    cudaGetSymbolAddress((void**)&xhi,  g_xhi);
    cudaGetSymbolAddress((void**)&xlo,  g_xlo);
    cudaGetSymbolAddress((void**)&whi,  g_whi);
    cudaGetSymbolAddress((void**)&wlo,  g_wlo);

    cudaFuncSetAttribute(lstm_scan_kernel<0>,
                         cudaFuncAttributeMaxDynamicSharedMemorySize, SCAN_SMEM);
    cudaFuncSetAttribute(lstm_scan_kernel<1>,
                         cudaFuncAttributeMaxDynamicSharedMemorySize, SCAN_SMEM);
    cudaFuncSetAttribute(gemm_mma_kernel,
                         cudaFuncAttributeMaxDynamicSharedMemorySize, GEMM_SMEM);

    const int NX4 = M_TOTAL * DD / 4;
    const int NWALL = 4 * (G4 * DD / 4);
    dim3 ggrid(4, 512, 2);
    const size_t WSET = (size_t)G4 * DD;

    // ---- all conversions up front ----
    cvt_hilo_kernel<<<(NX4 + 255) / 256, 256>>>(x, xhi, xlo, NX4);
    cvt_w4_kernel<<<(NWALL + 255) / 256, 256>>>(w_ih_l0, w_ih_l0r, w_ih_l1, w_ih_l1r,
                                                whi, wlo);

    // ---- layer 0 (weight slots 0,1) ----
    gemm_mma_kernel<<<ggrid, 256, GEMM_SMEM>>>(xhi, xlo, whi, wlo,
                                               b_ih_l0, b_hh_l0, b_ih_l0r, b_hh_l0r, gx);
    lstm_scan_kernel<0><<<128, 256, SCAN_SMEM>>>(gx, w_hh_l0, w_hh_l0r,
                                                 (float*)nullptr, xhi, xlo);

    // ---- layer 1 (weight slots 2,3) ----
    gemm_mma_kernel<<<ggrid, 256, GEMM_SMEM>>>(xhi, xlo, whi + 2 * WSET, wlo + 2 * WSET,
                                               b_ih_l1, b_hh_l1, b_ih_l1r, b_hh_l1r, gx);
    lstm_scan_kernel<1><<<128, 256, SCAN_SMEM>>>(gx, w_hh_l1, w_hh_l1r,
                                                 seq1, (__nv_bfloat16*)nullptr,
                                                 (__nv_bfloat16*)nullptr);

    // ---- emissions + CRF ----
    emissions_kernel<<<(M_TOTAL * 32 + 255) / 256, 256>>>(seq1, fc_w, fc_b, out + 1);
    crf_batch_kernel<<<BB, 128>>>(out + 1, tags, crf_start, crf_end, crf_trans, part);
    crf_reduce_kernel<<<1, 1>>>(part, out);
}

// round 14
// speedup vs baseline: 1.0310x; 1.0138x over previous
#include <cuda_runtime.h>
#include <cuda_bf16.h>
#include <math.h>
#include <cstdint>

#define BB 64
#define TT 1024
#define DD 256
#define HH 128
#define G4 512           // 4*H gate width
#define NTAGS 3
#define M_TOTAL (BB*TT)  // 65536

typedef unsigned long long u64;

// single dynamic-shared extern for all kernels
extern __shared__ char smem_raw[];

// ---------------- static scratch (no allocs allowed) ----------------
__device__ float g_gx[(size_t)2 * BB * TT * G4];        // [dir][b][t][512]
__device__ float g_seq1[(size_t)BB * TT * 2 * HH];      // layer1 output (fp32)
__device__ float g_part[BB];
__device__ __nv_bfloat16 g_xhi[(size_t)M_TOTAL * DD];   // A hi
__device__ __nv_bfloat16 g_xlo[(size_t)M_TOTAL * DD];   // A lo
__device__ __nv_bfloat16 g_whi[(size_t)4 * G4 * DD];    // W hi (l0,l0r,l1,l1r)
__device__ __nv_bfloat16 g_wlo[(size_t)4 * G4 * DD];    // W lo

// fast sigmoid / tanh (err ~2^-20)
__device__ __forceinline__ float fsig(float x) {
    return __fdividef(1.0f, 1.0f + __expf(-x));
}
__device__ __forceinline__ float ftanh_id(float x) {   // 2*sig(2x)-1
    return fmaf(2.0f, __fdividef(1.0f, 1.0f + __expf(-2.0f * x)), -1.0f);
}

// ---- packed f32x2 helpers ----
__device__ __forceinline__ void fma2(u64& d, u64 a, u64 b) {
    asm("fma.rn.f32x2 %0, %1, %2, %0;" : "+l"(d) : "l"(a), "l"(b));
}
__device__ __forceinline__ void add2(u64& d, u64 a, u64 b) {
    asm("add.rn.f32x2 %0, %1, %2;" : "=l"(d) : "l"(a), "l"(b));
}
__device__ __forceinline__ float2 unpk(u64 v) {
    float2 f; asm("mov.b64 {%0, %1}, %2;" : "=f"(f.x), "=f"(f.y) : "l"(v)); return f;
}

__device__ __forceinline__ uint32_t smem_u32(const void* p) {
    uint32_t a;
    asm("{ .reg .u64 t; cvta.to.shared.u64 t, %1; cvt.u32.u64 %0, t; }" : "=r"(a) : "l"(p));
    return a;
}

// ---- ldmatrix / mma.sync / cp.async (base sm_80+ ISA) ----
__device__ __forceinline__ void ldm_x4(uint32_t* r, uint32_t addr) {
    asm volatile("ldmatrix.sync.aligned.m8n8.x4.shared.b16 {%0,%1,%2,%3}, [%4];"
        : "=r"(r[0]), "=r"(r[1]), "=r"(r[2]), "=r"(r[3]) : "r"(addr));
}
__device__ __forceinline__ void mma_bf16(float* d, const uint32_t* a, uint32_t b0, uint32_t b1) {
    asm volatile("mma.sync.aligned.m16n8k16.row.col.f32.bf16.bf16.f32 "
        "{%0,%1,%2,%3}, {%4,%5,%6,%7}, {%8,%9}, {%0,%1,%2,%3};"
        : "+f"(d[0]), "+f"(d[1]), "+f"(d[2]), "+f"(d[3])
        : "r"(a[0]), "r"(a[1]), "r"(a[2]), "r"(a[3]), "r"(b0), "r"(b1));
}
__device__ __forceinline__ void cpa16(uint32_t dst, const void* src) {
    asm volatile("cp.async.cg.shared.global [%0], [%1], 16;" :: "r"(dst), "l"(src));
}

// =====================================================================
// fp32 -> bf16 hi/lo split (vectorized x4). One kernel converts x and
// the 4 W_ih matrices (segments after x).
// =====================================================================
__device__ __forceinline__ void cvt_one4(const float4& v,
                                         __nv_bfloat162* hp, __nv_bfloat162* lp, int i)
{
    __nv_bfloat16 h0 = __float2bfloat16(v.x), h1 = __float2bfloat16(v.y);
    __nv_bfloat16 h2 = __float2bfloat16(v.z), h3 = __float2bfloat16(v.w);
    hp[i * 2]     = __nv_bfloat162{h0, h1};
    hp[i * 2 + 1] = __nv_bfloat162{h2, h3};
    lp[i * 2]     = __nv_bfloat162{__float2bfloat16(v.x - __bfloat162float(h0)),
                                   __float2bfloat16(v.y - __bfloat162float(h1))};
    lp[i * 2 + 1] = __nv_bfloat162{__float2bfloat16(v.z - __bfloat162float(h2)),
                                   __float2bfloat16(v.w - __bfloat162float(h3))};
}

#define NX4 (M_TOTAL * DD / 4)     // 4194304 float4 in x
#define NW4 (G4 * DD / 4)          // 32768 float4 per W matrix

__global__ void cvt_all_kernel(const float* __restrict__ x,
                               const float* __restrict__ w0, const float* __restrict__ w1,
                               const float* __restrict__ w2, const float* __restrict__ w3,
                               __nv_bfloat16* __restrict__ xhi, __nv_bfloat16* __restrict__ xlo,
                               __nv_bfloat16* __restrict__ whi, __nv_bfloat16* __restrict__ wlo)
{
    int gid = blockIdx.x * 256 + threadIdx.x;
    if (gid < NX4) {
        float4 v = ((const float4*)x)[gid];
        cvt_one4(v, (__nv_bfloat162*)xhi, (__nv_bfloat162*)xlo, gid);
        return;
    }
    int r = gid - NX4;
    if (r >= 4 * NW4) return;
    int seg = r / NW4;
    int i = r - seg * NW4;
    const float* src = (seg == 0) ? w0 : (seg == 1) ? w1 : (seg == 2) ? w2 : w3;
    float4 v = ((const float4*)src)[i];
    __nv_bfloat162* hp = (__nv_bfloat162*)(whi + (size_t)seg * G4 * DD);
    __nv_bfloat162* lp = (__nv_bfloat162*)(wlo + (size_t)seg * G4 * DD);
    cvt_one4(v, hp, lp, i);
}

// =====================================================================
// bf16x3 GEMM via mma.sync m16n8k16, 3-stage cp.async pipeline,
// single barrier per chunk, prefetch depth 2. ROUND-11 exact (best).
// =====================================================================
#define KC    64
#define AROW  72                 // KC + 8 pad (bf16 elems); 144B row
#define TILEB (128 * AROW * 2)
#define STAGEB (2 * TILEB)       // 36864
#define NSTAGE 3
#define GEMM_SMEM (NSTAGE * STAGEB)   // 110592

__global__ __launch_bounds__(256, 2)
void gemm_mma_kernel(const __nv_bfloat16* __restrict__ xhi,
                     const __nv_bfloat16* __restrict__ xlo,
                     const __nv_bfloat16* __restrict__ whi,
                     const __nv_bfloat16* __restrict__ wlo,
                     const float* __restrict__ bihf, const float* __restrict__ bhhf,
                     const float* __restrict__ bihb, const float* __restrict__ bhhb,
                     float* __restrict__ gx)
{
    __shared__ float sbias[128];

    const int tid = threadIdx.x;
    const int lane = tid & 31;
    const int wid = tid >> 5;
    const int warp_m = wid >> 2;
    const int warp_n = wid & 3;
    const int m0 = blockIdx.y * 128;
    const int n0 = blockIdx.x * 128;
    const int dir = blockIdx.z;
    const __nv_bfloat16* Wh = whi + (size_t)dir * G4 * DD;
    const __nv_bfloat16* Wl = wlo + (size_t)dir * G4 * DD;
    const float* bih = dir ? bihb : bihf;
    const float* bhh = dir ? bhhb : bhhf;
    const uint32_t sdyn = smem_u32(smem_raw);

    if (tid < 128) sbias[tid] = bih[n0 + tid] + bhh[n0 + tid];

    float acc[4][4][4];
#pragma unroll
    for (int mt = 0; mt < 4; mt++)
#pragma unroll
        for (int nt = 0; nt < 4; nt++)
#pragma unroll
            for (int q = 0; q < 4; q++) acc[mt][nt][q] = 0.0f;

    uint32_t aOff[4], bOff[2];
#pragma unroll
    for (int mt = 0; mt < 4; mt++) {
        int row = warp_m * 64 + mt * 16 + (lane & 15);
        aOff[mt] = (uint32_t)((row * AROW + (lane >> 4) * 8) * 2);
    }
#pragma unroll
    for (int nh = 0; nh < 2; nh++) {
        int row = warp_n * 32 + nh * 16 + (lane & 15);
        bOff[nh] = (uint32_t)(TILEB + (row * AROW + (lane >> 4) * 8) * 2);
    }

    auto prefetch = [&](int c, int st) {
        const __nv_bfloat16* Asrc = (c >= 4 && c < 8) ? xlo : xhi;
        const __nv_bfloat16* Bsrc = (c >= 8) ? Wl : Wh;
        int kc = (c & 3) * KC;
        uint32_t base = sdyn + st * STAGEB;
#pragma unroll
        for (int i = 0; i < 4; i++) {
            int u = tid + i * 256;
            int row = u >> 3;
            int c8 = (u & 7) * 8;
            cpa16(base + (uint32_t)((row * AROW + c8) * 2),
                  Asrc + (size_t)(m0 + row) * DD + kc + c8);
            cpa16(base + (uint32_t)(TILEB + (row * AROW + c8) * 2),
                  Bsrc + (size_t)(n0 + row) * DD + kc + c8);
        }
        asm volatile("cp.async.commit_group;" ::: "memory");
    };

    prefetch(0, 0);
    prefetch(1, 1);
    for (int c = 0; c < 12; c++) {
        if (c < 11) {
            asm volatile("cp.async.wait_group 1;" ::: "memory");
        } else {
            asm volatile("cp.async.wait_group 0;" ::: "memory");
        }
        __syncthreads();   // all warps finished compute(c-1); stage (c+2)%3 free
        if (c + 2 < 12) prefetch(c + 2, (c + 2) % NSTAGE);

        uint32_t st = sdyn + (uint32_t)((c % NSTAGE) * STAGEB);
#pragma unroll
        for (int k16 = 0; k16 < KC / 16; k16++) {
            uint32_t a[4][4], b[2][4];
#pragma unroll
            for (int mt = 0; mt < 4; mt++)
                ldm_x4(a[mt], st + aOff[mt] + k16 * 32);
#pragma unroll
            for (int nh = 0; nh < 2; nh++)
                ldm_x4(b[nh], st + bOff[nh] + k16 * 32);
#pragma unroll
            for (int mt = 0; mt < 4; mt++)
#pragma unroll
                for (int nt = 0; nt < 4; nt++) {
                    int nh = nt >> 1, sub = nt & 1;
                    mma_bf16(acc[mt][nt], a[mt], b[nh][sub], b[nh][sub + 2]);
                }
        }
    }

    float* gxd = gx + (size_t)dir * M_TOTAL * G4;
#pragma unroll
    for (int mt = 0; mt < 4; mt++) {
        int r0 = m0 + warp_m * 64 + mt * 16 + (lane >> 2);
#pragma unroll
        for (int nt = 0; nt < 4; nt++) {
            int cidx = warp_n * 32 + nt * 8 + (lane & 3) * 2;
            int col = n0 + cidx;
            float2 v0 = make_float2(acc[mt][nt][0] + sbias[cidx],
                                    acc[mt][nt][1] + sbias[cidx + 1]);
            float2 v1 = make_float2(acc[mt][nt][2] + sbias[cidx],
                                    acc[mt][nt][3] + sbias[cidx + 1]);
            *(float2*)(gxd + (size_t)r0 * G4 + col) = v0;
            *(float2*)(gxd + (size_t)(r0 + 8) * G4 + col) = v1;
        }
    }
}

// =====================================================================
// LSTM scan (pair-thread; MODE compile-time). KREG 88 / KS 40 —
// measured optimum (804us/layer). FROZEN.
// =====================================================================
#define KREG 88
#define KS   40
#define NK4  (KS / 4)  // 10
#define SCAN_SMEM (NK4 * 2 * 256 * 16 + 2 * HH * 4)  // 81920 + 1024

template<int MODE>
__global__ __launch_bounds__(256, 1)
void lstm_scan_kernel(const float* __restrict__ gx,
                      const float* __restrict__ w_hh_f,
                      const float* __restrict__ w_hh_b,
                      float* __restrict__ outF,
                      __nv_bfloat16* __restrict__ outHi,
                      __nv_bfloat16* __restrict__ outLo)
{
    float* smem = (float*)smem_raw;
    const int bid = blockIdx.x;     // 0..127
    const int dir = bid >> 6;
    const int b   = bid & 63;
    const int j   = threadIdx.x;    // 0..255
    const int odd = j & 1;
    const int unit = j >> 1;        // 0..127
    const int row0 = unit + (odd << 7);   // i or f
    const int row1 = row0 + 256;          // g or o
    const float* W = dir ? w_hh_b : w_hh_f;

    ulonglong2* ws2 = (ulonglong2*)smem;            // [NK4][2][256]
    float* shb = smem + NK4 * 2 * 256 * 4;          // h double buffer [2][128]

    u64 wr0[KREG / 2], wr1[KREG / 2];
    {
        const u64* wp0 = (const u64*)(W + (size_t)row0 * HH);
        const u64* wp1 = (const u64*)(W + (size_t)row1 * HH);
#pragma unroll
        for (int p = 0; p < KREG / 2; p++) { wr0[p] = wp0[p]; wr1[p] = wp1[p]; }
    }
#pragma unroll
    for (int k4 = 0; k4 < NK4; k4++) {
        ws2[(k4 * 2 + 0) * 256 + j] = *(const ulonglong2*)(W + (size_t)row0 * HH + KREG + k4 * 4);
        ws2[(k4 * 2 + 1) * 256 + j] = *(const ulonglong2*)(W + (size_t)row1 * HH + KREG + k4 * 4);
    }
    if (j < HH) shb[j] = 0.0f;      // h_{-1} = 0 in buffer 0
    float c = 0.0f;
    __syncthreads();

    const float* gxb = gx + ((size_t)dir * BB + b) * TT * G4;
    const int dt = dir ? -1 : 1;
    int tt = dir ? (TT - 1) : 0;
    float g0 = gxb[(size_t)tt * G4 + row0];
    float g1 = gxb[(size_t)tt * G4 + row1];

    for (int t = 0; t < TT; t++) {
        int ttn = tt + dt;
        float gn0 = 0.f, gn1 = 0.f;
        if (t < TT - 1) {
            gn0 = gxb[(size_t)ttn * G4 + row0];
            gn1 = gxb[(size_t)ttn * G4 + row1];
        }

        const float* sh = shb + ((t & 1) << 7);        // read h_{t-1}
        float* shw = shb + (((t + 1) & 1) << 7);       // write h_t

        u64 a0a = 0ull, a0b = 0ull, a1a = 0ull, a1b = 0ull;
#pragma unroll
        for (int p = 0; p < KREG / 2; p += 2) {
            ulonglong2 h2 = *(const ulonglong2*)(sh + p * 2);
            fma2(a0a, wr0[p],     h2.x);
            fma2(a0b, wr0[p + 1], h2.y);
            fma2(a1a, wr1[p],     h2.x);
            fma2(a1b, wr1[p + 1], h2.y);
        }
#pragma unroll
        for (int k4 = 0; k4 < NK4; k4++) {
            ulonglong2 h2 = *(const ulonglong2*)(sh + KREG + k4 * 4);
            ulonglong2 w0 = ws2[(k4 * 2 + 0) * 256 + j];
            fma2(a0a, w0.x, h2.x);
            fma2(a0b, w0.y, h2.y);
            ulonglong2 w1 = ws2[(k4 * 2 + 1) * 256 + j];
            fma2(a1a, w1.x, h2.x);
            fma2(a1b, w1.y, h2.y);
        }
        u64 s0, s1;
        add2(s0, a0a, a0b);
        add2(s1, a1a, a1b);
        float2 v0 = unpk(s0), v1 = unpk(s1);
        float a0 = g0 + v0.x + v0.y;   // i or f pre-activation
        float a1 = g1 + v1.x + v1.y;   // g or o pre-activation

        float p0 = fsig(a0);
        float scale = odd ? 1.0f : 2.0f;
        float s = fsig(a1 * scale);
        float p1 = odd ? s : fmaf(2.0f, s, -1.0f);

        float q0 = __shfl_xor_sync(0xffffffffu, p0, 1);  // even gets f
        float q1 = __shfl_xor_sync(0xffffffffu, p1, 1);  // even gets o

        if (!odd) {
            c = q0 * c + p0 * p1;            // f*c + i*g
            float h = q1 * ftanh_id(c);      // o*tanh(c)
            shw[unit] = h;
            size_t oidx = ((size_t)b * TT + tt) * DD + dir * HH + unit;
            if (MODE == 0) {
                __nv_bfloat16 hh = __float2bfloat16(h);
                outHi[oidx] = hh;
                outLo[oidx] = __float2bfloat16(h - __bfloat162float(hh));
            } else {
                outF[oidx] = h;
            }
        }
        __syncthreads();

        g0 = gn0; g1 = gn1;
        tt = ttn;
    }
}

// =====================================================================
// Fused emissions + CRF: 64 blocks x 256 threads.
// Phase 1: warps compute emissions (fc_w slices in regs), write to
//          smem AND the output buffer.
// Phase 2: gold-path score (all threads, smem).
// Phase 3: forward DP (warp 0, lanes 0..2).
// =====================================================================
__global__ __launch_bounds__(256)
void emis_crf_kernel(const float* __restrict__ seq,
                     const float* __restrict__ fcw,
                     const float* __restrict__ fcb,
                     const int* __restrict__ tags,
                     const float* __restrict__ startv,
                     const float* __restrict__ endv,
                     const float* __restrict__ trans,
                     float* __restrict__ em_out,
                     float* __restrict__ part)
{
    __shared__ float sem[TT * NTAGS];   // 12 KB
    __shared__ int   stg[TT];           // 4 KB
    __shared__ float sred[8];
    __shared__ float strn[NTAGS * NTAGS];

    const int b = blockIdx.x;
    const int tid = threadIdx.x;
    const int lane = tid & 31;
    const int w = tid >> 5;

    if (tid < NTAGS * NTAGS) strn[tid] = trans[tid];

    // per-lane fc_w slices (8 floats per tag)
    float4 wa[NTAGS], wb[NTAGS];
#pragma unroll
    for (int tag = 0; tag < NTAGS; tag++) {
        wa[tag] = *(const float4*)(fcw + tag * 256 + lane * 8);
        wb[tag] = *(const float4*)(fcw + tag * 256 + lane * 8 + 4);
    }
    float fb0 = fcb[0], fb1 = fcb[1], fb2 = fcb[2];

    const float* sb = seq + (size_t)b * TT * DD;
    for (int t = w; t < TT; t += 8) {
        const float* row = sb + (size_t)t * DD + lane * 8;
        float4 xa = *(const float4*)(row);
        float4 xb = *(const float4*)(row + 4);
        float p0 = xa.x * wa[0].x + xa.y * wa[0].y + xa.z * wa[0].z + xa.w * wa[0].w
                 + xb.x * wb[0].x + xb.y * wb[0].y + xb.z * wb[0].z + xb.w * wb[0].w;
        float p1 = xa.x * wa[1].x + xa.y * wa[1].y + xa.z * wa[1].z + xa.w * wa[1].w
                 + xb.x * wb[1].x + xb.y * wb[1].y + xb.z * wb[1].z + xb.w * wb[1].w;
        float p2 = xa.x * wa[2].x + xa.y * wa[2].y + xa.z * wa[2].z + xa.w * wa[2].w
                 + xb.x * wb[2].x + xb.y * wb[2].y + xb.z * wb[2].z + xb.w * wb[2].w;
#pragma unroll
        for (int off = 16; off > 0; off >>= 1) {
            p0 += __shfl_xor_sync(0xffffffffu, p0, off);
            p1 += __shfl_xor_sync(0xffffffffu, p1, off);
            p2 += __shfl_xor_sync(0xffffffffu, p2, off);
        }
        if (lane == 0) {
            p0 += fb0; p1 += fb1; p2 += fb2;
            sem[t * NTAGS + 0] = p0;
            sem[t * NTAGS + 1] = p1;
            sem[t * NTAGS + 2] = p2;
            float* eo = em_out + ((size_t)b * TT + t) * NTAGS;
            eo[0] = p0; eo[1] = p1; eo[2] = p2;
        }
    }
    for (int i = tid; i < TT; i += 256) stg[i] = tags[(size_t)b * TT + i];
    __syncthreads();

    // gold-path score
    float s = 0.0f;
    for (int t = tid; t < TT; t += 256) {
        int tag = stg[t];
        s += sem[t * NTAGS + tag];
        if (t > 0) s += strn[stg[t - 1] * NTAGS + tag];
    }
#pragma unroll
    for (int off = 16; off > 0; off >>= 1)
        s += __shfl_xor_sync(0xffffffffu, s, off);
    if (lane == 0) sred[w] = s;
    __syncthreads();

    // forward DP on warp 0
    if (w == 0) {
        float alpha = -1e30f;
        float tr0 = 0.f, tr1 = 0.f, tr2 = 0.f, endl = 0.f;
        if (lane < NTAGS) {
            alpha = startv[lane] + sem[lane];
            tr0 = strn[0 * NTAGS + lane];
            tr1 = strn[1 * NTAGS + lane];
            tr2 = strn[2 * NTAGS + lane];
            endl = endv[lane];
        }
        for (int t = 1; t < TT; t++) {
            float a0 = __shfl_sync(0xffffffffu, alpha, 0);
            float a1 = __shfl_sync(0xffffffffu, alpha, 1);
            float a2 = __shfl_sync(0xffffffffu, alpha, 2);
            if (lane < NTAGS) {
                float v0 = a0 + tr0, v1 = a1 + tr1, v2 = a2 + tr2;
                float m = fmaxf(v0, fmaxf(v1, v2));
                alpha = sem[t * NTAGS + lane] + m +
                        logf(__expf(v0 - m) + __expf(v1 - m) + __expf(v2 - m));
            }
        }
        if (lane < NTAGS) alpha += endl;
        float a0 = __shfl_sync(0xffffffffu, alpha, 0);
        float a1 = __shfl_sync(0xffffffffu, alpha, 1);
        float a2 = __shfl_sync(0xffffffffu, alpha, 2);
        if (lane == 0) {
            float m = fmaxf(a0, fmaxf(a1, a2));
            float logZ = m + logf(__expf(a0 - m) + __expf(a1 - m) + __expf(a2 - m));
            float stotal = sred[0] + sred[1] + sred[2] + sred[3]
                         + sred[4] + sred[5] + sred[6] + sred[7];
            float num = stotal + startv[stg[0]] + endv[stg[TT - 1]];
            part[b] = num - logZ;
        }
    }
}

__global__ void crf_reduce_kernel(const float* __restrict__ part, float* __restrict__ out)
{
    float s = 0.0f;
    for (int i = 0; i < BB; i++) s += part[i];
    out[0] = -s / (float)BB;
}

// =====================================================================
extern "C" void kernel_launch(void* const* d_in, const int* in_sizes, int n_in,
                              void* d_out, int out_size)
{
    const float* x         = (const float*)d_in[0];
    const int*   tags      = (const int*)  d_in[1];
    const float* w_ih_l0   = (const float*)d_in[2];
    const float* w_hh_l0   = (const float*)d_in[3];
    const float* b_ih_l0   = (const float*)d_in[4];
    const float* b_hh_l0   = (const float*)d_in[5];
    const float* w_ih_l0r  = (const float*)d_in[6];
    const float* w_hh_l0r  = (const float*)d_in[7];
    const float* b_ih_l0r  = (const float*)d_in[8];
    const float* b_hh_l0r  = (const float*)d_in[9];
    const float* w_ih_l1   = (const float*)d_in[10];
    const float* w_hh_l1   = (const float*)d_in[11];
    const float* b_ih_l1   = (const float*)d_in[12];
    const float* b_hh_l1   = (const float*)d_in[13];
    const float* w_ih_l1r  = (const float*)d_in[14];
    const float* w_hh_l1r  = (const float*)d_in[15];
    const float* b_ih_l1r  = (const float*)d_in[16];
    const float* b_hh_l1r  = (const float*)d_in[17];
    const float* fc_w      = (const float*)d_in[18];
    const float* fc_b      = (const float*)d_in[19];
    const float* crf_start = (const float*)d_in[20];
    const float* crf_end   = (const float*)d_in[21];
    const float* crf_trans = (const float*)d_in[22];

    float* out = (float*)d_out;

    float *gx, *seq1, *part;
    __nv_bfloat16 *xhi, *xlo, *whi, *wlo;
    cudaGetSymbolAddress((void**)&gx,   g_gx);
    cudaGetSymbolAddress((void**)&seq1, g_seq1);
    cudaGetSymbolAddress((void**)&part, g_part);
    cudaGetSymbolAddress((void**)&xhi,  g_xhi);
    cudaGetSymbolAddress((void**)&xlo,  g_xlo);
    cudaGetSymbolAddress((void**)&whi,  g_whi);
    cudaGetSymbolAddress((void**)&wlo,  g_wlo);

    cudaFuncSetAttribute(lstm_scan_kernel<0>,
                         cudaFuncAttributeMaxDynamicSharedMemorySize, SCAN_SMEM);
    cudaFuncSetAttribute(lstm_scan_kernel<1>,
                         cudaFuncAttributeMaxDynamicSharedMemorySize, SCAN_SMEM);
    cudaFuncSetAttribute(gemm_mma_kernel,
                         cudaFuncAttributeMaxDynamicSharedMemorySize, GEMM_SMEM);

    dim3 ggrid(4, 512, 2);
    const size_t WSET = (size_t)G4 * DD;
    const int NCVT = NX4 + 4 * NW4;

    // ---- all conversions in one launch ----
    cvt_all_kernel<<<(NCVT + 255) / 256, 256>>>(x, w_ih_l0, w_ih_l0r, w_ih_l1, w_ih_l1r,
                                                xhi, xlo, whi, wlo);

    // ---- layer 0 (weight slots 0,1) ----
    gemm_mma_kernel<<<ggrid, 256, GEMM_SMEM>>>(xhi, xlo, whi, wlo,
                                               b_ih_l0, b_hh_l0, b_ih_l0r, b_hh_l0r, gx);
    lstm_scan_kernel<0><<<128, 256, SCAN_SMEM>>>(gx, w_hh_l0, w_hh_l0r,
                                                 (float*)nullptr, xhi, xlo);

    // ---- layer 1 (weight slots 2,3) ----
    gemm_mma_kernel<<<ggrid, 256, GEMM_SMEM>>>(xhi, xlo, whi + 2 * WSET, wlo + 2 * WSET,
                                               b_ih_l1, b_hh_l1, b_ih_l1r, b_hh_l1r, gx);
    lstm_scan_kernel<1><<<128, 256, SCAN_SMEM>>>(gx, w_hh_l1, w_hh_l1r,
                                                 seq1, (__nv_bfloat16*)nullptr,
                                                 (__nv_bfloat16*)nullptr);

    // ---- fused emissions + CRF ----
    emis_crf_kernel<<<BB, 256>>>(seq1, fc_w, fc_b, tags,
                                 crf_start, crf_end, crf_trans, out + 1, part);
    crf_reduce_kernel<<<1, 1>>>(part, out);
}

// round 15
// speedup vs baseline: 1.0574x; 1.0257x over previous
#include <cuda_runtime.h>
#include <cuda_bf16.h>
#include <math.h>
#include <cstdint>

#define BB 64
#define TT 1024
#define DD 256
#define HH 128
#define G4 512           // 4*H gate width
#define NTAGS 3
#define M_TOTAL (BB*TT)  // 65536

typedef unsigned long long u64;

// single dynamic-shared extern for all kernels
extern __shared__ char smem_raw[];

// ---------------- static scratch (no allocs allowed) ----------------
__device__ float g_gx[(size_t)2 * BB * TT * G4];        // [dir][b][t][512]
__device__ float g_seq1[(size_t)BB * TT * 2 * HH];      // layer1 output (fp32)
__device__ float g_part[BB];
__device__ __nv_bfloat16 g_xhi[(size_t)M_TOTAL * DD];   // A hi
__device__ __nv_bfloat16 g_xlo[(size_t)M_TOTAL * DD];   // A lo
__device__ __nv_bfloat16 g_whi[(size_t)4 * G4 * DD];    // W hi (l0,l0r,l1,l1r)
__device__ __nv_bfloat16 g_wlo[(size_t)4 * G4 * DD];    // W lo

// fast sigmoid / tanh (err ~2^-20)
__device__ __forceinline__ float fsig(float x) {
    return __fdividef(1.0f, 1.0f + __expf(-x));
}
__device__ __forceinline__ float ftanh_id(float x) {   // 2*sig(2x)-1
    return fmaf(2.0f, __fdividef(1.0f, 1.0f + __expf(-2.0f * x)), -1.0f);
}

// ---- packed f32x2 helpers ----
__device__ __forceinline__ void fma2(u64& d, u64 a, u64 b) {
    asm("fma.rn.f32x2 %0, %1, %2, %0;" : "+l"(d) : "l"(a), "l"(b));
}
__device__ __forceinline__ void add2(u64& d, u64 a, u64 b) {
    asm("add.rn.f32x2 %0, %1, %2;" : "=l"(d) : "l"(a), "l"(b));
}
__device__ __forceinline__ float2 unpk(u64 v) {
    float2 f; asm("mov.b64 {%0, %1}, %2;" : "=f"(f.x), "=f"(f.y) : "l"(v)); return f;
}

__device__ __forceinline__ uint32_t smem_u32(const void* p) {
    uint32_t a;
    asm("{ .reg .u64 t; cvta.to.shared.u64 t, %1; cvt.u32.u64 %0, t; }" : "=r"(a) : "l"(p));
    return a;
}

// ---- ldmatrix / mma.sync / cp.async (base sm_80+ ISA) ----
__device__ __forceinline__ void ldm_x4(uint32_t* r, uint32_t addr) {
    asm volatile("ldmatrix.sync.aligned.m8n8.x4.shared.b16 {%0,%1,%2,%3}, [%4];"
        : "=r"(r[0]), "=r"(r[1]), "=r"(r[2]), "=r"(r[3]) : "r"(addr));
}
__device__ __forceinline__ void mma_bf16(float* d, const uint32_t* a, uint32_t b0, uint32_t b1) {
    asm volatile("mma.sync.aligned.m16n8k16.row.col.f32.bf16.bf16.f32 "
        "{%0,%1,%2,%3}, {%4,%5,%6,%7}, {%8,%9}, {%0,%1,%2,%3};"
        : "+f"(d[0]), "+f"(d[1]), "+f"(d[2]), "+f"(d[3])
        : "r"(a[0]), "r"(a[1]), "r"(a[2]), "r"(a[3]), "r"(b0), "r"(b1));
}
__device__ __forceinline__ void cpa16(uint32_t dst, const void* src) {
    asm volatile("cp.async.cg.shared.global [%0], [%1], 16;" :: "r"(dst), "l"(src));
}

// =====================================================================
// fp32 -> bf16 hi/lo split (vectorized x4). One kernel converts x and
// the 4 W_ih matrices.
// =====================================================================
__device__ __forceinline__ void cvt_one4(const float4& v,
                                         __nv_bfloat162* hp, __nv_bfloat162* lp, int i)
{
    __nv_bfloat16 h0 = __float2bfloat16(v.x), h1 = __float2bfloat16(v.y);
    __nv_bfloat16 h2 = __float2bfloat16(v.z), h3 = __float2bfloat16(v.w);
    hp[i * 2]     = __nv_bfloat162{h0, h1};
    hp[i * 2 + 1] = __nv_bfloat162{h2, h3};
    lp[i * 2]     = __nv_bfloat162{__float2bfloat16(v.x - __bfloat162float(h0)),
                                   __float2bfloat16(v.y - __bfloat162float(h1))};
    lp[i * 2 + 1] = __nv_bfloat162{__float2bfloat16(v.z - __bfloat162float(h2)),
                                   __float2bfloat16(v.w - __bfloat162float(h3))};
}

#define NX4 (M_TOTAL * DD / 4)     // float4 count in x
#define NW4 (G4 * DD / 4)          // float4 per W matrix

__global__ void cvt_all_kernel(const float* __restrict__ x,
                               const float* __restrict__ w0, const float* __restrict__ w1,
                               const float* __restrict__ w2, const float* __restrict__ w3,
                               __nv_bfloat16* __restrict__ xhi, __nv_bfloat16* __restrict__ xlo,
                               __nv_bfloat16* __restrict__ whi, __nv_bfloat16* __restrict__ wlo)
{
    int gid = blockIdx.x * 256 + threadIdx.x;
    if (gid < NX4) {
        float4 v = ((const float4*)x)[gid];
        cvt_one4(v, (__nv_bfloat162*)xhi, (__nv_bfloat162*)xlo, gid);
        return;
    }
    int r = gid - NX4;
    if (r >= 4 * NW4) return;
    int seg = r / NW4;
    int i = r - seg * NW4;
    const float* src = (seg == 0) ? w0 : (seg == 1) ? w1 : (seg == 2) ? w2 : w3;
    float4 v = ((const float4*)src)[i];
    __nv_bfloat162* hp = (__nv_bfloat162*)(whi + (size_t)seg * G4 * DD);
    __nv_bfloat162* lp = (__nv_bfloat162*)(wlo + (size_t)seg * G4 * DD);
    cvt_one4(v, hp, lp, i);
}

// =====================================================================
// bf16x3 GEMM via mma.sync m16n8k16, 3-stage cp.async pipeline,
// single barrier per chunk, prefetch depth 2 (round-11 proven) +
// software-pipelined B fragments across k16.
// =====================================================================
#define KC    64
#define AROW  72                 // KC + 8 pad (bf16 elems); 144B row
#define TILEB (128 * AROW * 2)
#define STAGEB (2 * TILEB)       // 36864
#define NSTAGE 3
#define GEMM_SMEM (NSTAGE * STAGEB)   // 110592

__global__ __launch_bounds__(256, 2)
void gemm_mma_kernel(const __nv_bfloat16* __restrict__ xhi,
                     const __nv_bfloat16* __restrict__ xlo,
                     const __nv_bfloat16* __restrict__ whi,
                     const __nv_bfloat16* __restrict__ wlo,
                     const float* __restrict__ bihf, const float* __restrict__ bhhf,
                     const float* __restrict__ bihb, const float* __restrict__ bhhb,
                     float* __restrict__ gx)
{
    __shared__ float sbias[128];

    const int tid = threadIdx.x;
    const int lane = tid & 31;
    const int wid = tid >> 5;
    const int warp_m = wid >> 2;
    const int warp_n = wid & 3;
    const int m0 = blockIdx.y * 128;
    const int n0 = blockIdx.x * 128;
    const int dir = blockIdx.z;
    const __nv_bfloat16* Wh = whi + (size_t)dir * G4 * DD;
    const __nv_bfloat16* Wl = wlo + (size_t)dir * G4 * DD;
    const float* bih = dir ? bihb : bihf;
    const float* bhh = dir ? bhhb : bhhf;
    const uint32_t sdyn = smem_u32(smem_raw);

    if (tid < 128) sbias[tid] = bih[n0 + tid] + bhh[n0 + tid];

    float acc[4][4][4];
#pragma unroll
    for (int mt = 0; mt < 4; mt++)
#pragma unroll
        for (int nt = 0; nt < 4; nt++)
#pragma unroll
            for (int q = 0; q < 4; q++) acc[mt][nt][q] = 0.0f;

    uint32_t aOff[4], bOff[2];
#pragma unroll
    for (int mt = 0; mt < 4; mt++) {
        int row = warp_m * 64 + mt * 16 + (lane & 15);
        aOff[mt] = (uint32_t)((row * AROW + (lane >> 4) * 8) * 2);
    }
#pragma unroll
    for (int nh = 0; nh < 2; nh++) {
        int row = warp_n * 32 + nh * 16 + (lane & 15);
        bOff[nh] = (uint32_t)(TILEB + (row * AROW + (lane >> 4) * 8) * 2);
    }

    auto prefetch = [&](int c, int st) {
        const __nv_bfloat16* Asrc = (c >= 4 && c < 8) ? xlo : xhi;
        const __nv_bfloat16* Bsrc = (c >= 8) ? Wl : Wh;
        int kc = (c & 3) * KC;
        uint32_t base = sdyn + st * STAGEB;
#pragma unroll
        for (int i = 0; i < 4; i++) {
            int u = tid + i * 256;
            int row = u >> 3;
            int c8 = (u & 7) * 8;
            cpa16(base + (uint32_t)((row * AROW + c8) * 2),
                  Asrc + (size_t)(m0 + row) * DD + kc + c8);
            cpa16(base + (uint32_t)(TILEB + (row * AROW + c8) * 2),
                  Bsrc + (size_t)(n0 + row) * DD + kc + c8);
        }
        asm volatile("cp.async.commit_group;" ::: "memory");
    };

    prefetch(0, 0);
    prefetch(1, 1);
    for (int c = 0; c < 12; c++) {
        if (c < 11) {
            asm volatile("cp.async.wait_group 1;" ::: "memory");
        } else {
            asm volatile("cp.async.wait_group 0;" ::: "memory");
        }
        __syncthreads();   // all warps finished compute(c-1); stage (c+2)%3 free
        if (c + 2 < 12) prefetch(c + 2, (c + 2) % NSTAGE);

        uint32_t st = sdyn + (uint32_t)((c % NSTAGE) * STAGEB);

        // software pipeline: preload b fragments for k16=0
        uint32_t bf[2][4];
#pragma unroll
        for (int nh = 0; nh < 2; nh++)
            ldm_x4(bf[nh], st + bOff[nh]);

#pragma unroll
        for (int k16 = 0; k16 < KC / 16; k16++) {
            uint32_t a[4][4];
#pragma unroll
            for (int mt = 0; mt < 4; mt++)
                ldm_x4(a[mt], st + aOff[mt] + k16 * 32);

            uint32_t bn[2][4];
            if (k16 + 1 < KC / 16) {
#pragma unroll
                for (int nh = 0; nh < 2; nh++)
                    ldm_x4(bn[nh], st + bOff[nh] + (k16 + 1) * 32);
            }
#pragma unroll
            for (int mt = 0; mt < 4; mt++)
#pragma unroll
                for (int nt = 0; nt < 4; nt++) {
                    int nh = nt >> 1, sub = nt & 1;
                    mma_bf16(acc[mt][nt], a[mt], bf[nh][sub], bf[nh][sub + 2]);
                }
            if (k16 + 1 < KC / 16) {
#pragma unroll
                for (int nh = 0; nh < 2; nh++)
#pragma unroll
                    for (int q = 0; q < 4; q++) bf[nh][q] = bn[nh][q];
            }
        }
    }

    float* gxd = gx + (size_t)dir * M_TOTAL * G4;
#pragma unroll
    for (int mt = 0; mt < 4; mt++) {
        int r0 = m0 + warp_m * 64 + mt * 16 + (lane >> 2);
#pragma unroll
        for (int nt = 0; nt < 4; nt++) {
            int cidx = warp_n * 32 + nt * 8 + (lane & 3) * 2;
            int col = n0 + cidx;
            float2 v0 = make_float2(acc[mt][nt][0] + sbias[cidx],
                                    acc[mt][nt][1] + sbias[cidx + 1]);
            float2 v1 = make_float2(acc[mt][nt][2] + sbias[cidx],
                                    acc[mt][nt][3] + sbias[cidx + 1]);
            *(float2*)(gxd + (size_t)r0 * G4 + col) = v0;
            *(float2*)(gxd + (size_t)(r0 + 8) * G4 + col) = v1;
        }
    }
}

// =====================================================================
// LSTM scan (pair-thread; MODE compile-time). KREG 88 / KS 40 —
// measured optimum (804us/layer). FROZEN.
// =====================================================================
#define KREG 88
#define KS   40
#define NK4  (KS / 4)  // 10
#define SCAN_SMEM (NK4 * 2 * 256 * 16 + 2 * HH * 4)  // 81920 + 1024

template<int MODE>
__global__ __launch_bounds__(256, 1)
void lstm_scan_kernel(const float* __restrict__ gx,
                      const float* __restrict__ w_hh_f,
                      const float* __restrict__ w_hh_b,
                      float* __restrict__ outF,
                      __nv_bfloat16* __restrict__ outHi,
                      __nv_bfloat16* __restrict__ outLo)
{
    float* smem = (float*)smem_raw;
    const int bid = blockIdx.x;     // 0..127
    const int dir = bid >> 6;
    const int b   = bid & 63;
    const int j   = threadIdx.x;    // 0..255
    const int odd = j & 1;
    const int unit = j >> 1;        // 0..127
    const int row0 = unit + (odd << 7);   // i or f
    const int row1 = row0 + 256;          // g or o
    const float* W = dir ? w_hh_b : w_hh_f;

    ulonglong2* ws2 = (ulonglong2*)smem;            // [NK4][2][256]
    float* shb = smem + NK4 * 2 * 256 * 4;          // h double buffer [2][128]

    u64 wr0[KREG / 2], wr1[KREG / 2];
    {
        const u64* wp0 = (const u64*)(W + (size_t)row0 * HH);
        const u64* wp1 = (const u64*)(W + (size_t)row1 * HH);
#pragma unroll
        for (int p = 0; p < KREG / 2; p++) { wr0[p] = wp0[p]; wr1[p] = wp1[p]; }
    }
#pragma unroll
    for (int k4 = 0; k4 < NK4; k4++) {
        ws2[(k4 * 2 + 0) * 256 + j] = *(const ulonglong2*)(W + (size_t)row0 * HH + KREG + k4 * 4);
        ws2[(k4 * 2 + 1) * 256 + j] = *(const ulonglong2*)(W + (size_t)row1 * HH + KREG + k4 * 4);
    }
    if (j < HH) shb[j] = 0.0f;      // h_{-1} = 0 in buffer 0
    float c = 0.0f;
    __syncthreads();

    const float* gxb = gx + ((size_t)dir * BB + b) * TT * G4;
    const int dt = dir ? -1 : 1;
    int tt = dir ? (TT - 1) : 0;
    float g0 = gxb[(size_t)tt * G4 + row0];
    float g1 = gxb[(size_t)tt * G4 + row1];

    for (int t = 0; t < TT; t++) {
        int ttn = tt + dt;
        float gn0 = 0.f, gn1 = 0.f;
        if (t < TT - 1) {
            gn0 = gxb[(size_t)ttn * G4 + row0];
            gn1 = gxb[(size_t)ttn * G4 + row1];
        }

        const float* sh = shb + ((t & 1) << 7);        // read h_{t-1}
        float* shw = shb + (((t + 1) & 1) << 7);       // write h_t

        u64 a0a = 0ull, a0b = 0ull, a1a = 0ull, a1b = 0ull;
#pragma unroll
        for (int p = 0; p < KREG / 2; p += 2) {
            ulonglong2 h2 = *(const ulonglong2*)(sh + p * 2);
            fma2(a0a, wr0[p],     h2.x);
            fma2(a0b, wr0[p + 1], h2.y);
            fma2(a1a, wr1[p],     h2.x);
            fma2(a1b, wr1[p + 1], h2.y);
        }
#pragma unroll
        for (int k4 = 0; k4 < NK4; k4++) {
            ulonglong2 h2 = *(const ulonglong2*)(sh + KREG + k4 * 4);
            ulonglong2 w0 = ws2[(k4 * 2 + 0) * 256 + j];
            fma2(a0a, w0.x, h2.x);
            fma2(a0b, w0.y, h2.y);
            ulonglong2 w1 = ws2[(k4 * 2 + 1) * 256 + j];
            fma2(a1a, w1.x, h2.x);
            fma2(a1b, w1.y, h2.y);
        }
        u64 s0, s1;
        add2(s0, a0a, a0b);
        add2(s1, a1a, a1b);
        float2 v0 = unpk(s0), v1 = unpk(s1);
        float a0 = g0 + v0.x + v0.y;   // i or f pre-activation
        float a1 = g1 + v1.x + v1.y;   // g or o pre-activation

        float p0 = fsig(a0);
        float scale = odd ? 1.0f : 2.0f;
        float s = fsig(a1 * scale);
        float p1 = odd ? s : fmaf(2.0f, s, -1.0f);

        float q0 = __shfl_xor_sync(0xffffffffu, p0, 1);  // even gets f
        float q1 = __shfl_xor_sync(0xffffffffu, p1, 1);  // even gets o

        if (!odd) {
            c = q0 * c + p0 * p1;            // f*c + i*g
            float h = q1 * ftanh_id(c);      // o*tanh(c)
            shw[unit] = h;
            size_t oidx = ((size_t)b * TT + tt) * DD + dir * HH + unit;
            if (MODE == 0) {
                __nv_bfloat16 hh = __float2bfloat16(h);
                outHi[oidx] = hh;
                outLo[oidx] = __float2bfloat16(h - __bfloat162float(hh));
            } else {
                outF[oidx] = h;
            }
        }
        __syncthreads();

        g0 = gn0; g1 = gn1;
        tt = ttn;
    }
}

// =====================================================================
// Emissions: one warp per row (chip-wide, fast).
// =====================================================================
__global__ void emissions_kernel(const float* __restrict__ seq,
                                 const float* __restrict__ fcw,
                                 const float* __restrict__ fcb,
                                 float* __restrict__ em)
{
    int gw = (int)((blockIdx.x * blockDim.x + threadIdx.x) >> 5);
    int lane = threadIdx.x & 31;
    if (gw >= M_TOTAL) return;
    const float* row = seq + (size_t)gw * 256 + lane * 8;
    float4 xa = *(const float4*)(row);
    float4 xb = *(const float4*)(row + 4);
#pragma unroll
    for (int tag = 0; tag < NTAGS; tag++) {
        const float* w = fcw + tag * 256 + lane * 8;
        float4 wa = *(const float4*)(w);
        float4 wb = *(const float4*)(w + 4);
        float p = xa.x * wa.x + xa.y * wa.y + xa.z * wa.z + xa.w * wa.w
                + xb.x * wb.x + xb.y * wb.y + xb.z * wb.z + xb.w * wb.w;
#pragma unroll
        for (int off = 16; off > 0; off >>= 1)
            p += __shfl_xor_sync(0xffffffffu, p, off);
        if (lane == 0) em[(size_t)gw * NTAGS + tag] = p + fcb[tag];
    }
}

// =====================================================================
// CRF: smem-staged emissions + tags, fast exp / accurate log DP.
// =====================================================================
__global__ __launch_bounds__(128)
void crf_batch_kernel(const float* __restrict__ em,
                      const int* __restrict__ tags,
                      const float* __restrict__ startv,
                      const float* __restrict__ endv,
                      const float* __restrict__ trans,
                      float* __restrict__ part)
{
    __shared__ float sem[TT * NTAGS];   // 12 KB
    __shared__ int   stg[TT];           // 4 KB
    __shared__ float sred[4];

    const int b = blockIdx.x;
    const int tid = threadIdx.x;
    const int lane = tid & 31;
    const int wid = tid >> 5;
    const float* emb = em + (size_t)b * TT * NTAGS;
    const int* tg = tags + (size_t)b * TT;

    for (int i = tid; i < TT * NTAGS; i += 128) sem[i] = emb[i];
    for (int i = tid; i < TT; i += 128) stg[i] = tg[i];
    __syncthreads();

    float s = 0.0f;
    for (int t = tid; t < TT; t += 128) {
        int tag = stg[t];
        s += sem[t * NTAGS + tag];
        if (t > 0) s += trans[stg[t - 1] * NTAGS + tag];
    }
#pragma unroll
    for (int off = 16; off > 0; off >>= 1)
        s += __shfl_xor_sync(0xffffffffu, s, off);
    if (lane == 0) sred[wid] = s;
    __syncthreads();

    if (wid == 0) {
        float alpha = -1e30f;
        float tr0 = 0.f, tr1 = 0.f, tr2 = 0.f, endl = 0.f;
        if (lane < NTAGS) {
            alpha = startv[lane] + sem[lane];
            tr0 = trans[0 * NTAGS + lane];
            tr1 = trans[1 * NTAGS + lane];
            tr2 = trans[2 * NTAGS + lane];
            endl = endv[lane];
        }
        for (int t = 1; t < TT; t++) {
            float a0 = __shfl_sync(0xffffffffu, alpha, 0);
            float a1 = __shfl_sync(0xffffffffu, alpha, 1);
            float a2 = __shfl_sync(0xffffffffu, alpha, 2);
            if (lane < NTAGS) {
                float v0 = a0 + tr0, v1 = a1 + tr1, v2 = a2 + tr2;
                float m = fmaxf(v0, fmaxf(v1, v2));
                alpha = sem[t * NTAGS + lane] + m +
                        logf(__expf(v0 - m) + __expf(v1 - m) + __expf(v2 - m));
            }
        }
        if (lane < NTAGS) alpha += endl;
        float a0 = __shfl_sync(0xffffffffu, alpha, 0);
        float a1 = __shfl_sync(0xffffffffu, alpha, 1);
        float a2 = __shfl_sync(0xffffffffu, alpha, 2);
        if (lane == 0) {
            float m = fmaxf(a0, fmaxf(a1, a2));
            float logZ = m + logf(__expf(a0 - m) + __expf(a1 - m) + __expf(a2 - m));
            float stotal = sred[0] + sred[1] + sred[2] + sred[3];
            float num = stotal + startv[stg[0]] + endv[stg[TT - 1]];
            part[b] = num - logZ;
        }
    }
}

__global__ void crf_reduce_kernel(const float* __restrict__ part, float* __restrict__ out)
{
    int lane = threadIdx.x;
    float s = (lane < BB / 2) ? (part[lane] + part[lane + 32]) : 0.0f;
#pragma unroll
    for (int off = 16; off > 0; off >>= 1)
        s += __shfl_xor_sync(0xffffffffu, s, off);
    if (lane == 0) out[0] = -s / (float)BB;
}

// =====================================================================
extern "C" void kernel_launch(void* const* d_in, const int* in_sizes, int n_in,
                              void* d_out, int out_size)
{
    const float* x         = (const float*)d_in[0];
    const int*   tags      = (const int*)  d_in[1];
    const float* w_ih_l0   = (const float*)d_in[2];
    const float* w_hh_l0   = (const float*)d_in[3];
    const float* b_ih_l0   = (const float*)d_in[4];
    const float* b_hh_l0   = (const float*)d_in[5];
    const float* w_ih_l0r  = (const float*)d_in[6];
    const float* w_hh_l0r  = (const float*)d_in[7];
    const float* b_ih_l0r  = (const float*)d_in[8];
    const float* b_hh_l0r  = (const float*)d_in[9];
    const float* w_ih_l1   = (const float*)d_in[10];
    const float* w_hh_l1   = (const float*)d_in[11];
    const float* b_ih_l1   = (const float*)d_in[12];
    const float* b_hh_l1   = (const float*)d_in[13];
    const float* w_ih_l1r  = (const float*)d_in[14];
    const float* w_hh_l1r  = (const float*)d_in[15];
    const float* b_ih_l1r  = (const float*)d_in[16];
    const float* b_hh_l1r  = (const float*)d_in[17];
    const float* fc_w      = (const float*)d_in[18];
    const float* fc_b      = (const float*)d_in[19];
    const float* crf_start = (const float*)d_in[20];
    const float* crf_end   = (const float*)d_in[21];
    const float* crf_trans = (const float*)d_in[22];

    float* out = (float*)d_out;

    float *gx, *seq1, *part;
    __nv_bfloat16 *xhi, *xlo, *whi, *wlo;
    cudaGetSymbolAddress((void**)&gx,   g_gx);
    cudaGetSymbolAddress((void**)&seq1, g_seq1);
    cudaGetSymbolAddress((void**)&part, g_part);
    cudaGetSymbolAddress((void**)&xhi,  g_xhi);
    cudaGetSymbolAddress((void**)&xlo,  g_xlo);
    cudaGetSymbolAddress((void**)&whi,  g_whi);
    cudaGetSymbolAddress((void**)&wlo,  g_wlo);

    cudaFuncSetAttribute(lstm_scan_kernel<0>,
                         cudaFuncAttributeMaxDynamicSharedMemorySize, SCAN_SMEM);
    cudaFuncSetAttribute(lstm_scan_kernel<1>,
                         cudaFuncAttributeMaxDynamicSharedMemorySize, SCAN_SMEM);
    cudaFuncSetAttribute(gemm_mma_kernel,
                         cudaFuncAttributeMaxDynamicSharedMemorySize, GEMM_SMEM);

    dim3 ggrid(4, 512, 2);
    const size_t WSET = (size_t)G4 * DD;
    const int NCVT = NX4 + 4 * NW4;

    // ---- all conversions in one launch ----
    cvt_all_kernel<<<(NCVT + 255) / 256, 256>>>(x, w_ih_l0, w_ih_l0r, w_ih_l1, w_ih_l1r,
                                                xhi, xlo, whi, wlo);

    // ---- layer 0 (weight slots 0,1) ----
    gemm_mma_kernel<<<ggrid, 256, GEMM_SMEM>>>(xhi, xlo, whi, wlo,
                                               b_ih_l0, b_hh_l0, b_ih_l0r, b_hh_l0r, gx);
    lstm_scan_kernel<0><<<128, 256, SCAN_SMEM>>>(gx, w_hh_l0, w_hh_l0r,
                                                 (float*)nullptr, xhi, xlo);

    // ---- layer 1 (weight slots 2,3) ----
    gemm_mma_kernel<<<ggrid, 256, GEMM_SMEM>>>(xhi, xlo, whi + 2 * WSET, wlo + 2 * WSET,
                                               b_ih_l1, b_hh_l1, b_ih_l1r, b_hh_l1r, gx);
    lstm_scan_kernel<1><<<128, 256, SCAN_SMEM>>>(gx, w_hh_l1, w_hh_l1r,
                                                 seq1, (__nv_bfloat16*)nullptr,
                                                 (__nv_bfloat16*)nullptr);

    // ---- emissions + CRF ----
    emissions_kernel<<<(M_TOTAL * 32 + 255) / 256, 256>>>(seq1, fc_w, fc_b, out + 1);
    crf_batch_kernel<<<BB, 128>>>(out + 1, tags, crf_start, crf_end, crf_trans, part);
    crf_reduce_kernel<<<1, 32>>>(part, out);
}